// round 3
// baseline (speedup 1.0000x reference)
#include <cuda_runtime.h>
#include <math.h>

// ---------------- problem constants ----------------
#define LTOK 32768      // B * D*H*W
#define CDIM 192
#define NWIN 64
#define NHD  6
#define NTOK 512
#define HDD  32

typedef unsigned long long u64;

// ---------------- f32x2 packed helpers (sm_103a FFMA2) ----------------
__device__ __forceinline__ u64 fma2(u64 a, u64 b, u64 c) {
    u64 d; asm("fma.rn.f32x2 %0,%1,%2,%3;" : "=l"(d) : "l"(a), "l"(b), "l"(c)); return d;
}
__device__ __forceinline__ u64 mul2(u64 a, u64 b) {
    u64 d; asm("mul.rn.f32x2 %0,%1,%2;" : "=l"(d) : "l"(a), "l"(b)); return d;
}
__device__ __forceinline__ u64 pack2(float x, float y) {
    u64 r; asm("mov.b64 %0,{%1,%2};" : "=l"(r) : "f"(x), "f"(y)); return r;
}
__device__ __forceinline__ void unpack2(u64 a, float& x, float& y) {
    asm("mov.b64 {%0,%1},%2;" : "=f"(x), "=f"(y) : "l"(a));
}

// ---------------- device scratch (static, allocation-free) ----------------
__device__ float g_xn[LTOK * CDIM];
__device__ float g_q[NWIN * NHD * NTOK * HDD];
__device__ float g_k[NWIN * NHD * NTOK * HDD];
__device__ float g_v[NWIN * NHD * NTOK * HDD];
__device__ float g_attnout[LTOK * CDIM];
__device__ float g_h1[LTOK * 64];
__device__ float g_h2[LTOK * CDIM];
__device__ float g_x2[LTOK * CDIM];
__device__ float g_x2n[LTOK * CDIM];
__device__ float g_mh[LTOK * 768];
__device__ float g_w1t[27 * 192 * 64];
__device__ float g_w2t[27 * 64 * 192];
__device__ float g_bias[NHD * NTOK * NTOK];
__device__ float g_pp[128 * CDIM];
__device__ float g_ca[CDIM];

__device__ __forceinline__ float gelu_exact(float x) {
    return 0.5f * x * (1.0f + erff(x * 0.70710678118654752440f));
}

// ---------------- LayerNorm: one warp per row (C=192 = 32*6) ----------------
__global__ void ln_kernel(const float* __restrict__ x, const float* __restrict__ g,
                          const float* __restrict__ b, float* __restrict__ out) {
    int row  = blockIdx.x * blockDim.y + threadIdx.y;
    int lane = threadIdx.x;
    const float* xr = x + (size_t)row * CDIM;
    float v[6]; float s = 0.f, ss = 0.f;
#pragma unroll
    for (int i = 0; i < 6; i++) { v[i] = xr[lane + 32*i]; s += v[i]; ss += v[i]*v[i]; }
#pragma unroll
    for (int o = 16; o > 0; o >>= 1) {
        s  += __shfl_xor_sync(0xffffffffu, s, o);
        ss += __shfl_xor_sync(0xffffffffu, ss, o);
    }
    float mean = s * (1.f/192.f);
    float var  = ss * (1.f/192.f) - mean*mean;
    float rstd = rsqrtf(var + 1e-5f);
    float* orow = out + (size_t)row * CDIM;
#pragma unroll
    for (int i = 0; i < 6; i++)
        orow[lane + 32*i] = (v[i]-mean)*rstd*g[lane + 32*i] + b[lane + 32*i];
}

// ---------------- conv weight transpose: [co][ci][27] -> [kk][ci][co] ----------------
__global__ void wtrans_kernel(const float* __restrict__ w1, const float* __restrict__ w2) {
    int idx = blockIdx.x * 256 + threadIdx.x;
    if (idx < 64*192*27) {
        int co = idx / (192*27);
        int ci = (idx / 27) % 192;
        int kk = idx % 27;
        g_w1t[(kk*192 + ci)*64 + co] = w1[idx];
    }
    if (idx < 192*64*27) {
        int co = idx / (64*27);
        int ci = (idx / 27) % 64;
        int kk = idx % 27;
        g_w2t[(kk*64 + ci)*192 + co] = w2[idx];
    }
}

// ---------------- relative-position bias gather: g_bias[h][n][m] ----------------
__global__ void bias_kernel(const int* __restrict__ rpi, const float* __restrict__ rpb) {
    int idx = blockIdx.x * 256 + threadIdx.x;
    if (idx >= NHD * NTOK * NTOK) return;
    int h  = idx / (NTOK*NTOK);
    int nm = idx % (NTOK*NTOK);
    g_bias[idx] = rpb[rpi[nm]*NHD + h];
}

// ---------------- epilogue dispatch (shared by gemm2) ----------------
// EPI: 0 plain, 1 qkv-scatter, 2 proj+residual, 3 gelu, 4 final add
template<int EPI>
__device__ __forceinline__ void epi_store(int m, int n, float v, int Nn,
                                          float* __restrict__ out,
                                          const float* __restrict__ aux0) {
    if (EPI == 0) {
        out[(size_t)m*Nn + n] = v;
    } else if (EPI == 1) {
        int which = n / 192, c = n % 192;
        int head = c >> 5, hd = c & 31;
        int d = m >> 12, h = (m >> 6) & 63, w = m & 63;
        int wi = ((h >> 3) << 3) | (w >> 3);
        int nt = (d << 6) | ((h & 7) << 3) | (w & 7);
        size_t dst = ((size_t)((wi*NHD + head)*NTOK + nt))*HDD + hd;
        if (which == 0)      g_q[dst] = v * 0.17677669529663687f; // HD^-0.5
        else if (which == 1) g_k[dst] = v;
        else                 g_v[dst] = v;
    } else if (EPI == 2) {
        int wi = m >> 9, nt = m & 511;
        int d = nt >> 6;
        int h = ((wi >> 3) << 3) | ((nt >> 3) & 7);
        int w = ((wi & 7) << 3) | (nt & 7);
        size_t l = ((size_t)d << 12) | (h << 6) | w;
        size_t o = l*CDIM + n;
        g_x2[o] = aux0[o] + v + g_h2[o] * g_ca[n] * 0.01f;
    } else if (EPI == 3) {
        out[(size_t)m*Nn + n] = gelu_exact(v);
    } else { // EPI == 4
        out[(size_t)m*Nn + n] = g_x2[(size_t)m*CDIM + n] + v;
    }
}

// ---------------- 256x64 GEMM, 8x8 microtile, f32x2 FMAs ----------------
// out = A[M,K] @ Wt[N,K]^T + bias ; K multiple of 8
template<int EPI>
__global__ __launch_bounds__(256, 2)
void gemm2(const float* __restrict__ A, const float* __restrict__ Wt,
           const float* __restrict__ bias, float* __restrict__ out,
           int M, int Nn, int K, const float* __restrict__ aux0) {
    __shared__ __align__(16) float As[8][256];
    __shared__ __align__(16) u64   Bs[8][64];
    const int m0 = blockIdx.x * 256;
    const int n0 = blockIdx.y * 64;
    const int tid = threadIdx.x;
    const int tr = tid >> 3, tc = tid & 7;
    const float* arow = A + (size_t)(m0 + tid) * K;
    const int bn = tid & 63, bk = (tid >> 6) * 2;
    const float* bptr = Wt + (size_t)(n0 + bn) * K + bk;

    u64 acc[4][8];
#pragma unroll
    for (int i = 0; i < 4; i++)
#pragma unroll
        for (int j = 0; j < 8; j++) acc[i][j] = 0ull;

    const int nk = K >> 3;
    float4 pa0 = *(const float4*)(arow);
    float4 pa1 = *(const float4*)(arow + 4);
    float  pb0 = bptr[0], pb1 = bptr[1];

    for (int ks = 0; ks < nk; ks++) {
        As[0][tid] = pa0.x; As[1][tid] = pa0.y; As[2][tid] = pa0.z; As[3][tid] = pa0.w;
        As[4][tid] = pa1.x; As[5][tid] = pa1.y; As[6][tid] = pa1.z; As[7][tid] = pa1.w;
        Bs[bk][bn]   = pack2(pb0, pb0);
        Bs[bk+1][bn] = pack2(pb1, pb1);
        __syncthreads();
        if (ks + 1 < nk) {
            const float* a2 = arow + (ks + 1) * 8;
            pa0 = *(const float4*)(a2);
            pa1 = *(const float4*)(a2 + 4);
            const float* b2 = bptr + (ks + 1) * 8;
            pb0 = b2[0]; pb1 = b2[1];
        }
#pragma unroll
        for (int k = 0; k < 8; k++) {
            ulonglong2 a01 = *(const ulonglong2*)&As[k][tr*8];
            ulonglong2 a23 = *(const ulonglong2*)&As[k][tr*8 + 4];
            u64 am[4] = {a01.x, a01.y, a23.x, a23.y};
            ulonglong2 b0 = *(const ulonglong2*)&Bs[k][tc*8];
            ulonglong2 b1 = *(const ulonglong2*)&Bs[k][tc*8 + 2];
            ulonglong2 b2 = *(const ulonglong2*)&Bs[k][tc*8 + 4];
            ulonglong2 b3 = *(const ulonglong2*)&Bs[k][tc*8 + 6];
            u64 bb[8] = {b0.x, b0.y, b1.x, b1.y, b2.x, b2.y, b3.x, b3.y};
#pragma unroll
            for (int mp = 0; mp < 4; mp++)
#pragma unroll
                for (int nn = 0; nn < 8; nn++)
                    acc[mp][nn] = fma2(am[mp], bb[nn], acc[mp][nn]);
        }
        __syncthreads();
    }
#pragma unroll
    for (int mp = 0; mp < 4; mp++) {
        int m = m0 + tr*8 + mp*2;
#pragma unroll
        for (int nn = 0; nn < 8; nn++) {
            int n = n0 + tc*8 + nn;
            float v0, v1;
            unpack2(acc[mp][nn], v0, v1);
            float bsv = bias[n];
            epi_store<EPI>(m,     n, v0 + bsv, Nn, out, aux0);
            epi_store<EPI>(m + 1, n, v1 + bsv, Nn, out, aux0);
        }
    }
}

// ---------------- 3x3x3 conv: 256-token M tile, 64 N tile, f32x2 ----------------
template<bool DO_GELU>
__global__ __launch_bounds__(256, 2)
void conv2k(const float* __restrict__ in, const float* __restrict__ wt,
            const float* __restrict__ bias, float* __restrict__ out,
            int CIN, int COUT) {
    __shared__ __align__(16) float As[8][256];
    __shared__ __align__(16) u64   Bs[8][64];
    const int l0  = blockIdx.x * 256;
    const int co0 = blockIdx.y * 64;
    const int tid = threadIdx.x;
    const int tr = tid >> 3, tc = tid & 7;
    const int l = l0 + tid;
    const int d = l >> 12, h = (l >> 6) & 63, w = l & 63;
    const int bn = tid & 63, bk = (tid >> 6) * 2;

    u64 acc[4][8];
#pragma unroll
    for (int i = 0; i < 4; i++)
#pragma unroll
        for (int j = 0; j < 8; j++) acc[i][j] = 0ull;

    const int nkc = CIN >> 3;
    const int nks = 27 * nkc;

    // prefetch state for (kk=0, c0=0)
    float4 pa0, pa1; float pb0, pb1;
    {
        // kk = 0 -> dd=dh=dw=-1
        bool valid = ((unsigned)(d-1) < 8u) && ((unsigned)(h-1) < 64u) && ((unsigned)(w-1) < 64u);
        if (valid) {
            const float* p = in + (size_t)(l - 4096 - 64 - 1) * CIN;
            pa0 = *(const float4*)p; pa1 = *(const float4*)(p + 4);
        } else { pa0 = make_float4(0,0,0,0); pa1 = pa0; }
        const float* wk = wt + (size_t)bk * COUT + co0 + bn;
        pb0 = wk[0]; pb1 = wk[COUT];
    }

    int kk = 0, c0 = 0;
    for (int ks = 0; ks < nks; ks++) {
        As[0][tid] = pa0.x; As[1][tid] = pa0.y; As[2][tid] = pa0.z; As[3][tid] = pa0.w;
        As[4][tid] = pa1.x; As[5][tid] = pa1.y; As[6][tid] = pa1.z; As[7][tid] = pa1.w;
        Bs[bk][bn]   = pack2(pb0, pb0);
        Bs[bk+1][bn] = pack2(pb1, pb1);
        __syncthreads();
        // advance (kk, c0) and prefetch
        if (ks + 1 < nks) {
            int nc0 = c0 + 8, nkk = kk;
            if (nc0 == CIN) { nc0 = 0; nkk++; }
            int dd = nkk/9 - 1, dh = (nkk/3)%3 - 1, dw = nkk%3 - 1;
            bool valid = ((unsigned)(d+dd) < 8u) && ((unsigned)(h+dh) < 64u) && ((unsigned)(w+dw) < 64u);
            if (valid) {
                const float* p = in + (size_t)(l + dd*4096 + dh*64 + dw) * CIN + nc0;
                pa0 = *(const float4*)p; pa1 = *(const float4*)(p + 4);
            } else { pa0 = make_float4(0,0,0,0); pa1 = pa0; }
            const float* wk = wt + ((size_t)nkk*CIN + nc0 + bk) * COUT + co0 + bn;
            pb0 = wk[0]; pb1 = wk[COUT];
            kk = nkk; c0 = nc0;
        }
#pragma unroll
        for (int k = 0; k < 8; k++) {
            ulonglong2 a01 = *(const ulonglong2*)&As[k][tr*8];
            ulonglong2 a23 = *(const ulonglong2*)&As[k][tr*8 + 4];
            u64 am[4] = {a01.x, a01.y, a23.x, a23.y};
            ulonglong2 b0 = *(const ulonglong2*)&Bs[k][tc*8];
            ulonglong2 b1 = *(const ulonglong2*)&Bs[k][tc*8 + 2];
            ulonglong2 b2 = *(const ulonglong2*)&Bs[k][tc*8 + 4];
            ulonglong2 b3 = *(const ulonglong2*)&Bs[k][tc*8 + 6];
            u64 bb[8] = {b0.x, b0.y, b1.x, b1.y, b2.x, b2.y, b3.x, b3.y};
#pragma unroll
            for (int mp = 0; mp < 4; mp++)
#pragma unroll
                for (int nn = 0; nn < 8; nn++)
                    acc[mp][nn] = fma2(am[mp], bb[nn], acc[mp][nn]);
        }
        __syncthreads();
    }
#pragma unroll
    for (int mp = 0; mp < 4; mp++) {
        int pos = tr*8 + mp*2;
#pragma unroll
        for (int nn = 0; nn < 8; nn++) {
            int co = co0 + tc*8 + nn;
            float v0, v1;
            unpack2(acc[mp][nn], v0, v1);
            v0 += bias[co]; v1 += bias[co];
            if (DO_GELU) { v0 = gelu_exact(v0); v1 = gelu_exact(v1); }
            out[(size_t)(l0 + pos    )*COUT + co] = v0;
            out[(size_t)(l0 + pos + 1)*COUT + co] = v1;
        }
    }
}

// ---------------- global avg pool (stage 1) ----------------
__global__ void pool_kernel(const float* __restrict__ h2, float* __restrict__ partial) {
    int b = blockIdx.x, c = threadIdx.x;
    float s = 0.f;
    const float* base = h2 + (size_t)b * 256 * CDIM + c;
    for (int r = 0; r < 256; r++) s += base[(size_t)r * CDIM];
    partial[b*CDIM + c] = s;
}

// ---------------- channel attention (stage 2) ----------------
__global__ void ca_kernel(const float* __restrict__ partial,
                          const float* __restrict__ ca1w, const float* __restrict__ ca1b,
                          const float* __restrict__ ca2w, const float* __restrict__ ca2b) {
    __shared__ float pooled[CDIM];
    __shared__ float t6[6];
    int c = threadIdx.x;
    float s = 0.f;
    for (int b = 0; b < 128; b++) s += partial[b*CDIM + c];
    pooled[c] = s * (1.f/32768.f);
    __syncthreads();
    if (c < 6) {
        float a = ca1b[c];
        for (int i = 0; i < CDIM; i++) a += pooled[i] * ca1w[c*CDIM + i];
        t6[c] = fmaxf(a, 0.f);
    }
    __syncthreads();
    float a = ca2b[c];
#pragma unroll
    for (int j = 0; j < 6; j++) a += t6[j] * ca2w[c*6 + j];
    g_ca[c] = 1.f / (1.f + __expf(-a));
}

// ---------------- window attention: one block per (window, head), f32x2 ----------------
__global__ __launch_bounds__(512)
void attn_kernel() {
    extern __shared__ float sm[];
    float* sk = sm;
    float* sv = sm + NTOK*HDD;
    int wi = blockIdx.x / NHD, hh = blockIdx.x % NHD;
    size_t base = ((size_t)(wi*NHD + hh)) * NTOK * HDD;
    int tid = threadIdx.x;
    const float4* k4 = (const float4*)(g_k + base);
    const float4* v4 = (const float4*)(g_v + base);
    for (int i = tid; i < NTOK*HDD/4; i += 512) {
        ((float4*)sk)[i] = k4[i];
        ((float4*)sv)[i] = v4[i];
    }
    __syncthreads();
    const int r = tid;   // one query row per thread
    u64 qr2[16];
    const ulonglong2* q2 = (const ulonglong2*)(g_q + base + (size_t)r * HDD);
#pragma unroll
    for (int i = 0; i < 8; i++) {
        ulonglong2 t = q2[i];
        qr2[2*i] = t.x; qr2[2*i+1] = t.y;
    }
    const float* brow = g_bias + ((size_t)hh*NTOK + r) * NTOK;
    float mmax = -1e30f, lsum = 0.f;
    u64 o2[16];
#pragma unroll
    for (int i = 0; i < 16; i++) o2[i] = 0ull;

    for (int j4 = 0; j4 < NTOK; j4 += 4) {
        float4 bq = *(const float4*)&brow[j4];
        float bvv[4] = {bq.x, bq.y, bq.z, bq.w};
#pragma unroll
        for (int jj = 0; jj < 4; jj++) {
            int j = j4 + jj;
            const ulonglong2* kr = (const ulonglong2*)(sk + j*HDD);
            u64 s2 = 0ull;
#pragma unroll
            for (int i = 0; i < 8; i++) {
                ulonglong2 kv = kr[i];
                s2 = fma2(qr2[2*i],   kv.x, s2);
                s2 = fma2(qr2[2*i+1], kv.y, s2);
            }
            float slo, shi;
            unpack2(s2, slo, shi);
            float s = slo + shi + bvv[jj];
            const ulonglong2* vr = (const ulonglong2*)(sv + j*HDD);
            if (s <= mmax) {
                float p = __expf(s - mmax);
                lsum += p;
                u64 p2 = pack2(p, p);
#pragma unroll
                for (int i = 0; i < 8; i++) {
                    ulonglong2 vv = vr[i];
                    o2[2*i]   = fma2(vv.x, p2, o2[2*i]);
                    o2[2*i+1] = fma2(vv.y, p2, o2[2*i+1]);
                }
            } else {
                float sc = __expf(mmax - s);
                mmax = s;
                lsum = lsum*sc + 1.f;
                u64 sc2 = pack2(sc, sc);
#pragma unroll
                for (int i = 0; i < 8; i++) {
                    ulonglong2 vv = vr[i];
                    o2[2*i]   = fma2(o2[2*i],   sc2, vv.x);
                    o2[2*i+1] = fma2(o2[2*i+1], sc2, vv.y);
                }
            }
        }
    }
    float inv = 1.f / lsum;
    u64 inv2 = pack2(inv, inv);
    float* dst = g_attnout + ((size_t)(wi*NTOK + r))*CDIM + hh*HDD;
#pragma unroll
    for (int i = 0; i < 16; i++) {
        float a, b;
        unpack2(mul2(o2[i], inv2), a, b);
        dst[2*i]   = a;
        dst[2*i+1] = b;
    }
}

// ---------------- launch ----------------
extern "C" void kernel_launch(void* const* d_in, const int* in_sizes, int n_in,
                              void* d_out, int out_size) {
    const float* x     = (const float*)d_in[0];
    const float* n1g   = (const float*)d_in[1];
    const float* n1b   = (const float*)d_in[2];
    const float* qkvw  = (const float*)d_in[3];
    const float* qkvb  = (const float*)d_in[4];
    const float* rpb   = (const float*)d_in[5];
    const float* projw = (const float*)d_in[6];
    const float* projb = (const float*)d_in[7];
    const float* c1w   = (const float*)d_in[8];
    const float* c1b   = (const float*)d_in[9];
    const float* c2w   = (const float*)d_in[10];
    const float* c2b   = (const float*)d_in[11];
    const float* ca1w  = (const float*)d_in[12];
    const float* ca1b  = (const float*)d_in[13];
    const float* ca2w  = (const float*)d_in[14];
    const float* ca2b  = (const float*)d_in[15];
    const float* n2g   = (const float*)d_in[16];
    const float* n2b   = (const float*)d_in[17];
    const float* fc1w  = (const float*)d_in[18];
    const float* fc1b  = (const float*)d_in[19];
    const float* fc2w  = (const float*)d_in[20];
    const float* fc2b  = (const float*)d_in[21];
    const int*   rpi   = (const int*)d_in[22];
    float* out = (float*)d_out;

    float *p_xn, *p_h1, *p_h2, *p_x2, *p_x2n, *p_mh, *p_pp, *p_attnout, *p_w1t, *p_w2t;
    cudaGetSymbolAddress((void**)&p_xn,      g_xn);
    cudaGetSymbolAddress((void**)&p_h1,      g_h1);
    cudaGetSymbolAddress((void**)&p_h2,      g_h2);
    cudaGetSymbolAddress((void**)&p_x2,      g_x2);
    cudaGetSymbolAddress((void**)&p_x2n,     g_x2n);
    cudaGetSymbolAddress((void**)&p_mh,      g_mh);
    cudaGetSymbolAddress((void**)&p_pp,      g_pp);
    cudaGetSymbolAddress((void**)&p_attnout, g_attnout);
    cudaGetSymbolAddress((void**)&p_w1t,     g_w1t);
    cudaGetSymbolAddress((void**)&p_w2t,     g_w2t);

    cudaFuncSetAttribute(attn_kernel, cudaFuncAttributeMaxDynamicSharedMemorySize,
                         2 * NTOK * HDD * (int)sizeof(float));

    // 1) LN1
    ln_kernel<<<4096, dim3(32, 8)>>>(x, n1g, n1b, p_xn);
    // 2) one-shot transposes / gathers
    wtrans_kernel<<<1296, 256>>>(c1w, c2w);
    bias_kernel<<<(NHD*NTOK*NTOK + 255)/256, 256>>>(rpi, rpb);
    // 3) QKV projection -> window layout
    gemm2<1><<<dim3(128, 9), 256>>>(p_xn, qkvw, qkvb, nullptr, LTOK, 576, CDIM, nullptr);
    // 4) conv branch
    conv2k<true ><<<dim3(128, 1), 256>>>(p_xn, p_w1t, c1b, p_h1, 192, 64);
    conv2k<false><<<dim3(128, 3), 256>>>(p_h1, p_w2t, c2b, p_h2, 64, 192);
    pool_kernel<<<128, CDIM>>>(p_h2, p_pp);
    ca_kernel<<<1, CDIM>>>(p_pp, ca1w, ca1b, ca2w, ca2b);
    // 5) window attention
    attn_kernel<<<NWIN * NHD, 512, 2 * NTOK * HDD * (int)sizeof(float)>>>();
    // 6) proj + window reverse + residual + conv*0.01 -> g_x2
    gemm2<2><<<dim3(128, 3), 256>>>(p_attnout, projw, projb, nullptr, LTOK, CDIM, CDIM, x);
    // 7) LN2 + MLP
    ln_kernel<<<4096, dim3(32, 8)>>>(p_x2, n2g, n2b, p_x2n);
    gemm2<3><<<dim3(128, 12), 256>>>(p_x2n, fc1w, fc1b, p_mh, LTOK, 768, CDIM, nullptr);
    gemm2<4><<<dim3(128, 3), 256>>>(p_mh, fc2w, fc2b, out, LTOK, CDIM, 768, nullptr);
}

// round 4
// speedup vs baseline: 2.6613x; 2.6613x over previous
#include <cuda_runtime.h>
#include <cuda_bf16.h>
#include <math.h>

// ---------------- problem constants ----------------
#define LTOK 32768      // B * D*H*W
#define CDIM 192
#define NWIN 64
#define NHD  6
#define NTOK 512
#define HDD  32

typedef unsigned int u32;
typedef __nv_bfloat16 bf16;

// ---------------- device scratch (static, allocation-free) ----------------
// fp32
__device__ float g_q[NWIN * NHD * NTOK * HDD];
__device__ float g_k[NWIN * NHD * NTOK * HDD];
__device__ float g_v[NWIN * NHD * NTOK * HDD];
__device__ float g_h2[LTOK * CDIM];
__device__ float g_x2[LTOK * CDIM];
__device__ float g_bias[NHD * NTOK * NTOK];
__device__ float g_pp[128 * CDIM];
__device__ float g_ca[CDIM];
// bf16 split-cat activations: [hi | hi | lo], row stride 3K
__device__ bf16 g_xnc [LTOK * 576];      // K=192
__device__ bf16 g_aoc [LTOK * 576];      // K=192 (attention out)
__device__ bf16 g_x2nc[LTOK * 576];      // K=192
__device__ bf16 g_h1c [LTOK * 192];      // K=64
__device__ bf16 g_mhc [(size_t)LTOK * 2304];  // K=768
// bf16 split-cat weights: [hi | lo | hi], row stride 3K
__device__ bf16 g_qkvwc[576 * 576];
__device__ bf16 g_projwc[192 * 576];
__device__ bf16 g_fc1wc[768 * 576];
__device__ bf16 g_fc2wc[192 * 2304];
__device__ bf16 g_w1c[27 * 64 * 576];    // [kk][co][3*192]
__device__ bf16 g_w2c[27 * 192 * 192];   // [kk][co][3*64]

__device__ __forceinline__ float gelu_exact(float x) {
    return 0.5f * x * (1.0f + erff(x * 0.70710678118654752440f));
}

// write activation split-cat: [hi, hi, lo]
__device__ __forceinline__ void store_cat(bf16* __restrict__ rowp, int K, int k, float v) {
    bf16 h = __float2bfloat16(v);
    bf16 l = __float2bfloat16(v - __bfloat162float(h));
    rowp[k] = h; rowp[K + k] = h; rowp[2*K + k] = l;
}

// ---------------- mma / ldmatrix helpers ----------------
__device__ __forceinline__ void ldm4(u32& r0, u32& r1, u32& r2, u32& r3, const bf16* p) {
    u32 addr = (u32)__cvta_generic_to_shared(p);
    asm volatile("ldmatrix.sync.aligned.m8n8.x4.shared.b16 {%0,%1,%2,%3},[%4];"
                 : "=r"(r0), "=r"(r1), "=r"(r2), "=r"(r3) : "r"(addr));
}
__device__ __forceinline__ void mma16816(float* c, const u32* a, const u32* b) {
    asm volatile(
        "mma.sync.aligned.m16n8k16.row.col.f32.bf16.bf16.f32 "
        "{%0,%1,%2,%3},{%4,%5,%6,%7},{%8,%9},{%0,%1,%2,%3};"
        : "+f"(c[0]), "+f"(c[1]), "+f"(c[2]), "+f"(c[3])
        : "r"(a[0]), "r"(a[1]), "r"(a[2]), "r"(a[3]), "r"(b[0]), "r"(b[1]));
}

// ---------------- LayerNorm + split-cat write ----------------
__global__ void ln_split_kernel(const float* __restrict__ x, const float* __restrict__ g,
                                const float* __restrict__ b, bf16* __restrict__ dst) {
    int row  = blockIdx.x * blockDim.y + threadIdx.y;
    int lane = threadIdx.x;
    const float* xr = x + (size_t)row * CDIM;
    float v[6]; float s = 0.f, ss = 0.f;
#pragma unroll
    for (int i = 0; i < 6; i++) { v[i] = xr[lane + 32*i]; s += v[i]; ss += v[i]*v[i]; }
#pragma unroll
    for (int o = 16; o > 0; o >>= 1) {
        s  += __shfl_xor_sync(0xffffffffu, s, o);
        ss += __shfl_xor_sync(0xffffffffu, ss, o);
    }
    float mean = s * (1.f/192.f);
    float var  = ss * (1.f/192.f) - mean*mean;
    float rstd = rsqrtf(var + 1e-5f);
    bf16* orow = dst + (size_t)row * 576;
#pragma unroll
    for (int i = 0; i < 6; i++) {
        int c = lane + 32*i;
        store_cat(orow, 192, c, (v[i]-mean)*rstd*g[c] + b[c]);
    }
}

// ---------------- weight split kernels ----------------
// dense: src [N][K] fp32 -> dst [N][3K] pattern [hi, lo, hi]
__global__ void wsplit_dense(const float* __restrict__ src, bf16* __restrict__ dst,
                             int K, int total) {
    int idx = blockIdx.x * 256 + threadIdx.x;
    if (idx >= total) return;
    int n = idx / K, k = idx % K;
    float v = src[idx];
    bf16 h = __float2bfloat16(v);
    bf16 l = __float2bfloat16(v - __bfloat162float(h));
    bf16* rowp = dst + (size_t)n * 3 * K;
    rowp[k] = h; rowp[K + k] = l; rowp[2*K + k] = h;
}
// conv1: src [64][192][27] -> g_w1c [27][64][3*192] pattern [hi, lo, hi]
__global__ void wsplit_conv1(const float* __restrict__ src) {
    int idx = blockIdx.x * 256 + threadIdx.x;
    if (idx >= 64*192*27) return;
    int co = idx / (192*27), ci = (idx / 27) % 192, kk = idx % 27;
    float v = src[idx];
    bf16 h = __float2bfloat16(v);
    bf16 l = __float2bfloat16(v - __bfloat162float(h));
    bf16* rowp = g_w1c + ((size_t)kk*64 + co) * 576;
    rowp[ci] = h; rowp[192 + ci] = l; rowp[384 + ci] = h;
}
// conv2: src [192][64][27] -> g_w2c [27][192][3*64]
__global__ void wsplit_conv2(const float* __restrict__ src) {
    int idx = blockIdx.x * 256 + threadIdx.x;
    if (idx >= 192*64*27) return;
    int co = idx / (64*27), ci = (idx / 27) % 64, kk = idx % 27;
    float v = src[idx];
    bf16 h = __float2bfloat16(v);
    bf16 l = __float2bfloat16(v - __bfloat162float(h));
    bf16* rowp = g_w2c + ((size_t)kk*192 + co) * 192;
    rowp[ci] = h; rowp[64 + ci] = l; rowp[128 + ci] = h;
}

// ---------------- relative-position bias gather: g_bias[h][n][m] ----------------
__global__ void bias_kernel(const int* __restrict__ rpi, const float* __restrict__ rpb) {
    int idx = blockIdx.x * 256 + threadIdx.x;
    if (idx >= NHD * NTOK * NTOK) return;
    int h  = idx / (NTOK*NTOK);
    int nm = idx % (NTOK*NTOK);
    g_bias[idx] = rpb[rpi[nm]*NHD + h];
}

// ---------------- epilogue dispatch ----------------
// EPI: 1 qkv-scatter, 2 proj+residual, 3 fc1 gelu->cat, 4 final add
template<int EPI>
__device__ __forceinline__ void epi_store(int m, int n, float v,
                                          float* __restrict__ out,
                                          const float* __restrict__ aux0) {
    if (EPI == 1) {
        int which = n / 192, c = n % 192;
        int head = c >> 5, hd = c & 31;
        int d = m >> 12, h = (m >> 6) & 63, w = m & 63;
        int wi = ((h >> 3) << 3) | (w >> 3);
        int nt = (d << 6) | ((h & 7) << 3) | (w & 7);
        size_t dst = ((size_t)((wi*NHD + head)*NTOK + nt))*HDD + hd;
        if (which == 0)      g_q[dst] = v * 0.17677669529663687f; // HD^-0.5
        else if (which == 1) g_k[dst] = v;
        else                 g_v[dst] = v;
    } else if (EPI == 2) {
        int wi = m >> 9, nt = m & 511;
        int d = nt >> 6;
        int h = ((wi >> 3) << 3) | ((nt >> 3) & 7);
        int w = ((wi & 7) << 3) | (nt & 7);
        size_t l = ((size_t)d << 12) | (h << 6) | w;
        size_t o = l*CDIM + n;
        g_x2[o] = aux0[o] + v + g_h2[o] * g_ca[n] * 0.01f;
    } else if (EPI == 3) {
        store_cat(g_mhc + (size_t)m * 2304, 768, n, gelu_exact(v));
    } else { // EPI == 4
        out[(size_t)m*CDIM + n] = g_x2[(size_t)m*CDIM + n] + v;
    }
}

// ---------------- bf16 tensor-core GEMM: 128x64 block tile ----------------
// out = Acat[M,Kc] @ Wcat[N,Kc]^T (+bias, epilogue). Kc multiple of 32.
template<int EPI>
__global__ __launch_bounds__(256)
void gemm_bf16(const bf16* __restrict__ A, const bf16* __restrict__ B,
               const float* __restrict__ bias, float* __restrict__ out,
               int Kc, const float* __restrict__ aux0) {
    __shared__ __align__(16) bf16 As[128][40];
    __shared__ __align__(16) bf16 Bs[64][40];
    const int m0 = blockIdx.x * 128;
    const int n0 = blockIdx.y * 64;
    const int tid = threadIdx.x;
    const int lane = tid & 31, warp = tid >> 5;
    const int warp_m = warp & 3, warp_n = warp >> 2;

    const bf16* aptr = A + (size_t)(m0 + (tid >> 1)) * Kc + (tid & 1) * 16;
    const bf16* bptr = B + (size_t)(n0 + (tid >> 2)) * Kc + (tid & 3) * 8;
    bf16* as_st = &As[tid >> 1][(tid & 1) * 16];
    bf16* bs_st = &Bs[tid >> 2][(tid & 3) * 8];

    // ldmatrix lane-address components
    const int a_r  = warp_m*32 + (lane & 7) + ((lane >> 3) & 1) * 8;
    const int a_c8 = (lane >> 4) * 8;
    const int b_r  = warp_n*32 + (lane >> 4) * 8 + (lane & 7);
    const int b_c8 = ((lane >> 3) & 1) * 8;

    float acc[2][4][4];
#pragma unroll
    for (int i = 0; i < 2; i++)
#pragma unroll
        for (int j = 0; j < 4; j++)
#pragma unroll
            for (int t = 0; t < 4; t++) acc[i][j][t] = 0.f;

    const int nk = Kc >> 5;
    uint4 pa0 = *(const uint4*)aptr;
    uint4 pa1 = *(const uint4*)(aptr + 8);
    uint4 pb  = *(const uint4*)bptr;

    for (int ks = 0; ks < nk; ks++) {
        *(uint4*)as_st       = pa0;
        *(uint4*)(as_st + 8) = pa1;
        *(uint4*)bs_st       = pb;
        __syncthreads();
        if (ks + 1 < nk) {
            pa0 = *(const uint4*)(aptr + (ks+1)*32);
            pa1 = *(const uint4*)(aptr + (ks+1)*32 + 8);
            pb  = *(const uint4*)(bptr + (ks+1)*32);
        }
#pragma unroll
        for (int s = 0; s < 2; s++) {
            u32 afr[2][4], bfr[4][2];
#pragma unroll
            for (int mt = 0; mt < 2; mt++)
                ldm4(afr[mt][0], afr[mt][1], afr[mt][2], afr[mt][3],
                     &As[a_r + mt*16][s*16 + a_c8]);
#pragma unroll
            for (int np = 0; np < 2; np++)
                ldm4(bfr[2*np][0], bfr[2*np][1], bfr[2*np+1][0], bfr[2*np+1][1],
                     &Bs[b_r + np*16][s*16 + b_c8]);
#pragma unroll
            for (int mt = 0; mt < 2; mt++)
#pragma unroll
                for (int nt = 0; nt < 4; nt++)
                    mma16816(acc[mt][nt], afr[mt], bfr[nt]);
        }
        __syncthreads();
    }
#pragma unroll
    for (int mt = 0; mt < 2; mt++) {
        int mrow = m0 + warp_m*32 + mt*16 + (lane >> 2);
#pragma unroll
        for (int nt = 0; nt < 4; nt++) {
            int ncol = n0 + warp_n*32 + nt*8 + 2*(lane & 3);
            epi_store<EPI>(mrow,     ncol,     acc[mt][nt][0] + bias[ncol],   out, aux0);
            epi_store<EPI>(mrow,     ncol + 1, acc[mt][nt][1] + bias[ncol+1], out, aux0);
            epi_store<EPI>(mrow + 8, ncol,     acc[mt][nt][2] + bias[ncol],   out, aux0);
            epi_store<EPI>(mrow + 8, ncol + 1, acc[mt][nt][3] + bias[ncol+1], out, aux0);
        }
    }
}

// ---------------- bf16 tensor-core 3x3x3 conv ----------------
// CEPI: 0 = gelu -> g_h1c cat (K=64), 1 = plain fp32 -> g_h2
template<int CEPI>
__global__ __launch_bounds__(256)
void conv_bf16(const bf16* __restrict__ Acat, const bf16* __restrict__ Wcat,
               const float* __restrict__ bias, int Kc, int COUT) {
    __shared__ __align__(16) bf16 As[128][40];
    __shared__ __align__(16) bf16 Bs[64][40];
    const int l0 = blockIdx.x * 128;
    const int n0 = blockIdx.y * 64;
    const int tid = threadIdx.x;
    const int lane = tid & 31, warp = tid >> 5;
    const int warp_m = warp & 3, warp_n = warp >> 2;

    const int arow = tid >> 1, acolv = (tid & 1) * 16;
    const int l = l0 + arow;
    const int d = l >> 12, hh = (l >> 6) & 63, ww = l & 63;
    const int brow = tid >> 2, bcolv = (tid & 3) * 8;
    bf16* as_st = &As[arow][acolv];
    bf16* bs_st = &Bs[brow][bcolv];

    const int a_r  = warp_m*32 + (lane & 7) + ((lane >> 3) & 1) * 8;
    const int a_c8 = (lane >> 4) * 8;
    const int b_r  = warp_n*32 + (lane >> 4) * 8 + (lane & 7);
    const int b_c8 = ((lane >> 3) & 1) * 8;

    float acc[2][4][4];
#pragma unroll
    for (int i = 0; i < 2; i++)
#pragma unroll
        for (int j = 0; j < 4; j++)
#pragma unroll
            for (int t = 0; t < 4; t++) acc[i][j][t] = 0.f;

    const int nchunk = Kc >> 5;
    const int nks = 27 * nchunk;

    uint4 pa0, pa1, pb;
    // prefetch ks = 0
    {
        // kk=0 -> offsets -1,-1,-1
        bool valid = ((unsigned)(d-1) < 8u) && ((unsigned)(hh-1) < 64u) && ((unsigned)(ww-1) < 64u);
        if (valid) {
            const bf16* p = Acat + (size_t)(l - 4096 - 64 - 1) * Kc + acolv;
            pa0 = *(const uint4*)p; pa1 = *(const uint4*)(p + 8);
        } else { pa0 = make_uint4(0,0,0,0); pa1 = pa0; }
        pb = *(const uint4*)(Wcat + (size_t)(n0 + brow) * Kc + bcolv);
    }

    for (int ks = 0; ks < nks; ks++) {
        *(uint4*)as_st       = pa0;
        *(uint4*)(as_st + 8) = pa1;
        *(uint4*)bs_st       = pb;
        __syncthreads();
        if (ks + 1 < nks) {
            int ksn = ks + 1;
            int kk = ksn / nchunk, c0 = (ksn % nchunk) * 32;
            int dd = kk/9 - 1, dh = (kk/3)%3 - 1, dw = kk%3 - 1;
            bool valid = ((unsigned)(d+dd) < 8u) && ((unsigned)(hh+dh) < 64u) && ((unsigned)(ww+dw) < 64u);
            if (valid) {
                const bf16* p = Acat + (size_t)(l + dd*4096 + dh*64 + dw) * Kc + c0 + acolv;
                pa0 = *(const uint4*)p; pa1 = *(const uint4*)(p + 8);
            } else { pa0 = make_uint4(0,0,0,0); pa1 = pa0; }
            pb = *(const uint4*)(Wcat + ((size_t)kk*COUT + n0 + brow) * Kc + c0 + bcolv);
        }
#pragma unroll
        for (int s = 0; s < 2; s++) {
            u32 afr[2][4], bfr[4][2];
#pragma unroll
            for (int mt = 0; mt < 2; mt++)
                ldm4(afr[mt][0], afr[mt][1], afr[mt][2], afr[mt][3],
                     &As[a_r + mt*16][s*16 + a_c8]);
#pragma unroll
            for (int np = 0; np < 2; np++)
                ldm4(bfr[2*np][0], bfr[2*np][1], bfr[2*np+1][0], bfr[2*np+1][1],
                     &Bs[b_r + np*16][s*16 + b_c8]);
#pragma unroll
            for (int mt = 0; mt < 2; mt++)
#pragma unroll
                for (int nt = 0; nt < 4; nt++)
                    mma16816(acc[mt][nt], afr[mt], bfr[nt]);
        }
        __syncthreads();
    }
#pragma unroll
    for (int mt = 0; mt < 2; mt++) {
        int row = warp_m*32 + mt*16 + (lane >> 2);
#pragma unroll
        for (int nt = 0; nt < 4; nt++) {
            int co = n0 + warp_n*32 + nt*8 + 2*(lane & 3);
#pragma unroll
            for (int q = 0; q < 4; q++) {
                int tok = l0 + row + (q >> 1) * 8;
                int c   = co + (q & 1);
                float v = acc[mt][nt][q] + bias[c];
                if (CEPI == 0) store_cat(g_h1c + (size_t)tok * 192, 64, c, gelu_exact(v));
                else           g_h2[(size_t)tok * CDIM + c] = v;
            }
        }
    }
}

// ---------------- global avg pool (stage 1) ----------------
__global__ void pool_kernel(const float* __restrict__ h2, float* __restrict__ partial) {
    int b = blockIdx.x, c = threadIdx.x;
    float s = 0.f;
    const float* base = h2 + (size_t)b * 256 * CDIM + c;
    for (int r = 0; r < 256; r++) s += base[(size_t)r * CDIM];
    partial[b*CDIM + c] = s;
}

// ---------------- channel attention (stage 2) ----------------
__global__ void ca_kernel(const float* __restrict__ partial,
                          const float* __restrict__ ca1w, const float* __restrict__ ca1b,
                          const float* __restrict__ ca2w, const float* __restrict__ ca2b) {
    __shared__ float pooled[CDIM];
    __shared__ float t6[6];
    int c = threadIdx.x;
    float s = 0.f;
    for (int b = 0; b < 128; b++) s += partial[b*CDIM + c];
    pooled[c] = s * (1.f/32768.f);
    __syncthreads();
    if (c < 6) {
        float a = ca1b[c];
        for (int i = 0; i < CDIM; i++) a += pooled[i] * ca1w[c*CDIM + i];
        t6[c] = fmaxf(a, 0.f);
    }
    __syncthreads();
    float a = ca2b[c];
#pragma unroll
    for (int j = 0; j < 6; j++) a += t6[j] * ca2w[c*6 + j];
    g_ca[c] = 1.f / (1.f + __expf(-a));
}

// ---------------- window attention (R1 scalar, proven) + cat epilogue ----------------
__global__ __launch_bounds__(512)
void attn_kernel() {
    extern __shared__ float sm[];
    float* sk = sm;
    float* sv = sm + NTOK*HDD;
    int wi = blockIdx.x / NHD, hh = blockIdx.x % NHD;
    size_t base = ((size_t)(wi*NHD + hh)) * NTOK * HDD;
    int tid = threadIdx.x;
    const float4* k4 = (const float4*)(g_k + base);
    const float4* v4 = (const float4*)(g_v + base);
    for (int i = tid; i < NTOK*HDD/4; i += 512) {
        ((float4*)sk)[i] = k4[i];
        ((float4*)sv)[i] = v4[i];
    }
    __syncthreads();
    const int r = tid;
    float qr[32];
    const float4* q4 = (const float4*)(g_q + base + (size_t)r * HDD);
#pragma unroll
    for (int i = 0; i < 8; i++) {
        float4 t = q4[i];
        qr[4*i] = t.x; qr[4*i+1] = t.y; qr[4*i+2] = t.z; qr[4*i+3] = t.w;
    }
    const float* brow = g_bias + ((size_t)hh*NTOK + r) * NTOK;
    float mmax = -1e30f, lsum = 0.f;
    float o[32];
#pragma unroll
    for (int i = 0; i < 32; i++) o[i] = 0.f;
    for (int j4 = 0; j4 < NTOK; j4 += 4) {
        float4 bq = *(const float4*)&brow[j4];
        float bvv[4] = {bq.x, bq.y, bq.z, bq.w};
#pragma unroll
        for (int jj = 0; jj < 4; jj++) {
            int j = j4 + jj;
            const float4* kr = (const float4*)(sk + j*HDD);
            float s = bvv[jj];
#pragma unroll
            for (int i = 0; i < 8; i++) {
                float4 kv = kr[i];
                s += qr[4*i]*kv.x + qr[4*i+1]*kv.y + qr[4*i+2]*kv.z + qr[4*i+3]*kv.w;
            }
            const float4* vr = (const float4*)(sv + j*HDD);
            if (s <= mmax) {
                float p = __expf(s - mmax);
                lsum += p;
#pragma unroll
                for (int i = 0; i < 8; i++) {
                    float4 vv = vr[i];
                    o[4*i]   += p*vv.x; o[4*i+1] += p*vv.y;
                    o[4*i+2] += p*vv.z; o[4*i+3] += p*vv.w;
                }
            } else {
                float sc = __expf(mmax - s);
                mmax = s;
                lsum = lsum*sc + 1.f;
#pragma unroll
                for (int i = 0; i < 8; i++) {
                    float4 vv = vr[i];
                    o[4*i]   = o[4*i]*sc   + vv.x;
                    o[4*i+1] = o[4*i+1]*sc + vv.y;
                    o[4*i+2] = o[4*i+2]*sc + vv.z;
                    o[4*i+3] = o[4*i+3]*sc + vv.w;
                }
            }
        }
    }
    float inv = 1.f / lsum;
    bf16* dst = g_aoc + (size_t)(wi*NTOK + r) * 576;
#pragma unroll
    for (int i = 0; i < 32; i++)
        store_cat(dst, 192, hh*HDD + i, o[i]*inv);
}

// ---------------- launch ----------------
extern "C" void kernel_launch(void* const* d_in, const int* in_sizes, int n_in,
                              void* d_out, int out_size) {
    const float* x     = (const float*)d_in[0];
    const float* n1g   = (const float*)d_in[1];
    const float* n1b   = (const float*)d_in[2];
    const float* qkvw  = (const float*)d_in[3];
    const float* qkvb  = (const float*)d_in[4];
    const float* rpb   = (const float*)d_in[5];
    const float* projw = (const float*)d_in[6];
    const float* projb = (const float*)d_in[7];
    const float* c1w   = (const float*)d_in[8];
    const float* c1b   = (const float*)d_in[9];
    const float* c2w   = (const float*)d_in[10];
    const float* c2b   = (const float*)d_in[11];
    const float* ca1w  = (const float*)d_in[12];
    const float* ca1b  = (const float*)d_in[13];
    const float* ca2w  = (const float*)d_in[14];
    const float* ca2b  = (const float*)d_in[15];
    const float* n2g   = (const float*)d_in[16];
    const float* n2b   = (const float*)d_in[17];
    const float* fc1w  = (const float*)d_in[18];
    const float* fc1b  = (const float*)d_in[19];
    const float* fc2w  = (const float*)d_in[20];
    const float* fc2b  = (const float*)d_in[21];
    const int*   rpi   = (const int*)d_in[22];
    float* out = (float*)d_out;

    bf16 *p_xnc, *p_aoc, *p_x2nc, *p_h1c, *p_mhc;
    bf16 *p_qkvwc, *p_projwc, *p_fc1wc, *p_fc2wc, *p_w1c, *p_w2c;
    float *p_h2, *p_x2, *p_pp;
    cudaGetSymbolAddress((void**)&p_xnc,    g_xnc);
    cudaGetSymbolAddress((void**)&p_aoc,    g_aoc);
    cudaGetSymbolAddress((void**)&p_x2nc,   g_x2nc);
    cudaGetSymbolAddress((void**)&p_h1c,    g_h1c);
    cudaGetSymbolAddress((void**)&p_mhc,    g_mhc);
    cudaGetSymbolAddress((void**)&p_qkvwc,  g_qkvwc);
    cudaGetSymbolAddress((void**)&p_projwc, g_projwc);
    cudaGetSymbolAddress((void**)&p_fc1wc,  g_fc1wc);
    cudaGetSymbolAddress((void**)&p_fc2wc,  g_fc2wc);
    cudaGetSymbolAddress((void**)&p_w1c,    g_w1c);
    cudaGetSymbolAddress((void**)&p_w2c,    g_w2c);
    cudaGetSymbolAddress((void**)&p_h2,     g_h2);
    cudaGetSymbolAddress((void**)&p_x2,     g_x2);
    cudaGetSymbolAddress((void**)&p_pp,     g_pp);

    cudaFuncSetAttribute(attn_kernel, cudaFuncAttributeMaxDynamicSharedMemorySize,
                         2 * NTOK * HDD * (int)sizeof(float));

    // 1) weight splits + bias gather (small)
    wsplit_dense<<<(576*192 + 255)/256, 256>>>(qkvw, p_qkvwc, 192, 576*192);
    wsplit_dense<<<(192*192 + 255)/256, 256>>>(projw, p_projwc, 192, 192*192);
    wsplit_dense<<<(768*192 + 255)/256, 256>>>(fc1w, p_fc1wc, 192, 768*192);
    wsplit_dense<<<(192*768 + 255)/256, 256>>>(fc2w, p_fc2wc, 768, 192*768);
    wsplit_conv1<<<(64*192*27 + 255)/256, 256>>>(c1w);
    wsplit_conv2<<<(192*64*27 + 255)/256, 256>>>(c2w);
    bias_kernel<<<(NHD*NTOK*NTOK + 255)/256, 256>>>(rpi, rpb);
    // 2) LN1 -> split-cat
    ln_split_kernel<<<4096, dim3(32, 8)>>>(x, n1g, n1b, p_xnc);
    // 3) QKV projection (tensor core) -> window-layout q/k/v
    gemm_bf16<1><<<dim3(256, 9), 256>>>(p_xnc, p_qkvwc, qkvb, nullptr, 576, nullptr);
    // 4) conv branch (tensor core)
    conv_bf16<0><<<dim3(256, 1), 256>>>(p_xnc, p_w1c, c1b, 576, 64);
    conv_bf16<1><<<dim3(256, 3), 256>>>(p_h1c, p_w2c, c2b, 192, 192);
    pool_kernel<<<128, CDIM>>>(p_h2, p_pp);
    ca_kernel<<<1, CDIM>>>(p_pp, ca1w, ca1b, ca2w, ca2b);
    // 5) window attention (scalar) -> split-cat
    attn_kernel<<<NWIN * NHD, 512, 2 * NTOK * HDD * (int)sizeof(float)>>>();
    // 6) proj + window reverse + residual + conv*0.01 -> g_x2
    gemm_bf16<2><<<dim3(256, 3), 256>>>(p_aoc, p_projwc, projb, nullptr, 576, x);
    // 7) LN2 + MLP
    ln_split_kernel<<<4096, dim3(32, 8)>>>(p_x2, n2g, n2b, p_x2nc);
    gemm_bf16<3><<<dim3(256, 12), 256>>>(p_x2nc, p_fc1wc, fc1b, nullptr, 576, nullptr);
    gemm_bf16<4><<<dim3(256, 3), 256>>>(p_mhc, p_fc2wc, fc2b, out, 2304, nullptr);
}

// round 5
// speedup vs baseline: 2.9998x; 1.1272x over previous
#include <cuda_runtime.h>
#include <cuda_bf16.h>
#include <math.h>

// ---------------- problem constants ----------------
#define LTOK 32768      // B * D*H*W
#define CDIM 192
#define NWIN 64
#define NHD  6
#define NTOK 512
#define HDD  32

typedef unsigned int u32;
typedef __nv_bfloat16 bf16;

// ---------------- device scratch (static, allocation-free) ----------------
__device__ float g_q[NWIN * NHD * NTOK * HDD];
__device__ float g_k[NWIN * NHD * NTOK * HDD];
__device__ float g_v[NWIN * NHD * NTOK * HDD];
__device__ float g_h2[LTOK * CDIM];
__device__ float g_x2[LTOK * CDIM];
__device__ float g_bias[NHD * NTOK * NTOK];
__device__ float g_pp[128 * CDIM];
__device__ float g_ca[CDIM];
// bf16 split-cat activations: [hi | hi | lo], row stride 3K
__device__ bf16 g_xnc [LTOK * 576];      // K=192
__device__ bf16 g_aoc [LTOK * 576];      // K=192 (attention out)
__device__ bf16 g_x2nc[LTOK * 576];      // K=192
__device__ bf16 g_h1c [LTOK * 192];      // K=64
__device__ bf16 g_mhc [(size_t)LTOK * 2304];  // K=768
// bf16 split-cat weights: [hi | lo | hi], row stride 3K
__device__ bf16 g_qkvwc[576 * 576];
__device__ bf16 g_projwc[192 * 576];
__device__ bf16 g_fc1wc[768 * 576];
__device__ bf16 g_fc2wc[192 * 2304];
__device__ bf16 g_w1c[27 * 64 * 576];    // [kk][co][3*192]
__device__ bf16 g_w2c[27 * 192 * 192];   // [kk][co][3*64]

__device__ __forceinline__ float gelu_exact(float x) {
    return 0.5f * x * (1.0f + erff(x * 0.70710678118654752440f));
}

// write activation split-cat: [hi, hi, lo]
__device__ __forceinline__ void store_cat(bf16* __restrict__ rowp, int K, int k, float v) {
    bf16 h = __float2bfloat16(v);
    bf16 l = __float2bfloat16(v - __bfloat162float(h));
    rowp[k] = h; rowp[K + k] = h; rowp[2*K + k] = l;
}

// ---------------- mma / ldmatrix / cp.async helpers ----------------
__device__ __forceinline__ void ldm4(u32& r0, u32& r1, u32& r2, u32& r3, const bf16* p) {
    u32 addr = (u32)__cvta_generic_to_shared(p);
    asm volatile("ldmatrix.sync.aligned.m8n8.x4.shared.b16 {%0,%1,%2,%3},[%4];"
                 : "=r"(r0), "=r"(r1), "=r"(r2), "=r"(r3) : "r"(addr));
}
__device__ __forceinline__ void mma16816(float* c, const u32* a, const u32* b) {
    asm volatile(
        "mma.sync.aligned.m16n8k16.row.col.f32.bf16.bf16.f32 "
        "{%0,%1,%2,%3},{%4,%5,%6,%7},{%8,%9},{%0,%1,%2,%3};"
        : "+f"(c[0]), "+f"(c[1]), "+f"(c[2]), "+f"(c[3])
        : "r"(a[0]), "r"(a[1]), "r"(a[2]), "r"(a[3]), "r"(b[0]), "r"(b[1]));
}
__device__ __forceinline__ void cp16(bf16* dst, const bf16* src) {
    u32 d = (u32)__cvta_generic_to_shared(dst);
    asm volatile("cp.async.cg.shared.global [%0],[%1],16;" :: "r"(d), "l"(src));
}
__device__ __forceinline__ void cp16z(bf16* dst, const bf16* src, bool v) {
    u32 d = (u32)__cvta_generic_to_shared(dst);
    int sz = v ? 16 : 0;
    asm volatile("cp.async.cg.shared.global [%0],[%1],16,%2;" :: "r"(d), "l"(src), "r"(sz));
}
#define CP_COMMIT() asm volatile("cp.async.commit_group;")
#define CP_WAIT1()  asm volatile("cp.async.wait_group 1;")

// ---------------- LayerNorm + split-cat write ----------------
__global__ void ln_split_kernel(const float* __restrict__ x, const float* __restrict__ g,
                                const float* __restrict__ b, bf16* __restrict__ dst) {
    int row  = blockIdx.x * blockDim.y + threadIdx.y;
    int lane = threadIdx.x;
    const float* xr = x + (size_t)row * CDIM;
    float v[6]; float s = 0.f, ss = 0.f;
#pragma unroll
    for (int i = 0; i < 6; i++) { v[i] = xr[lane + 32*i]; s += v[i]; ss += v[i]*v[i]; }
#pragma unroll
    for (int o = 16; o > 0; o >>= 1) {
        s  += __shfl_xor_sync(0xffffffffu, s, o);
        ss += __shfl_xor_sync(0xffffffffu, ss, o);
    }
    float mean = s * (1.f/192.f);
    float var  = ss * (1.f/192.f) - mean*mean;
    float rstd = rsqrtf(var + 1e-5f);
    bf16* orow = dst + (size_t)row * 576;
#pragma unroll
    for (int i = 0; i < 6; i++) {
        int c = lane + 32*i;
        store_cat(orow, 192, c, (v[i]-mean)*rstd*g[c] + b[c]);
    }
}

// ---------------- weight split kernels ----------------
__global__ void wsplit_dense(const float* __restrict__ src, bf16* __restrict__ dst,
                             int K, int total) {
    int idx = blockIdx.x * 256 + threadIdx.x;
    if (idx >= total) return;
    int n = idx / K, k = idx % K;
    float v = src[idx];
    bf16 h = __float2bfloat16(v);
    bf16 l = __float2bfloat16(v - __bfloat162float(h));
    bf16* rowp = dst + (size_t)n * 3 * K;
    rowp[k] = h; rowp[K + k] = l; rowp[2*K + k] = h;
}
__global__ void wsplit_conv1(const float* __restrict__ src) {
    int idx = blockIdx.x * 256 + threadIdx.x;
    if (idx >= 64*192*27) return;
    int co = idx / (192*27), ci = (idx / 27) % 192, kk = idx % 27;
    float v = src[idx];
    bf16 h = __float2bfloat16(v);
    bf16 l = __float2bfloat16(v - __bfloat162float(h));
    bf16* rowp = g_w1c + ((size_t)kk*64 + co) * 576;
    rowp[ci] = h; rowp[192 + ci] = l; rowp[384 + ci] = h;
}
__global__ void wsplit_conv2(const float* __restrict__ src) {
    int idx = blockIdx.x * 256 + threadIdx.x;
    if (idx >= 192*64*27) return;
    int co = idx / (64*27), ci = (idx / 27) % 64, kk = idx % 27;
    float v = src[idx];
    bf16 h = __float2bfloat16(v);
    bf16 l = __float2bfloat16(v - __bfloat162float(h));
    bf16* rowp = g_w2c + ((size_t)kk*192 + co) * 192;
    rowp[ci] = h; rowp[64 + ci] = l; rowp[128 + ci] = h;
}

// ---------------- relative-position bias gather ----------------
__global__ void bias_kernel(const int* __restrict__ rpi, const float* __restrict__ rpb) {
    int idx = blockIdx.x * 256 + threadIdx.x;
    if (idx >= NHD * NTOK * NTOK) return;
    int h  = idx / (NTOK*NTOK);
    int nm = idx % (NTOK*NTOK);
    g_bias[idx] = rpb[rpi[nm]*NHD + h];
}

// ---------------- epilogue dispatch ----------------
// EPI: 1 qkv-scatter, 2 proj+residual, 3 fc1 gelu->cat, 4 final add
template<int EPI>
__device__ __forceinline__ void epi_store(int m, int n, float v,
                                          float* __restrict__ out,
                                          const float* __restrict__ aux0) {
    if (EPI == 1) {
        int which = n / 192, c = n % 192;
        int head = c >> 5, hd = c & 31;
        int d = m >> 12, h = (m >> 6) & 63, w = m & 63;
        int wi = ((h >> 3) << 3) | (w >> 3);
        int nt = (d << 6) | ((h & 7) << 3) | (w & 7);
        size_t dst = ((size_t)((wi*NHD + head)*NTOK + nt))*HDD + hd;
        if (which == 0)      g_q[dst] = v * 0.17677669529663687f; // HD^-0.5
        else if (which == 1) g_k[dst] = v;
        else                 g_v[dst] = v;
    } else if (EPI == 2) {
        int wi = m >> 9, nt = m & 511;
        int d = nt >> 6;
        int h = ((wi >> 3) << 3) | ((nt >> 3) & 7);
        int w = ((wi & 7) << 3) | (nt & 7);
        size_t l = ((size_t)d << 12) | (h << 6) | w;
        size_t o = l*CDIM + n;
        g_x2[o] = aux0[o] + v + g_h2[o] * g_ca[n] * 0.01f;
    } else if (EPI == 3) {
        store_cat(g_mhc + (size_t)m * 2304, 768, n, gelu_exact(v));
    } else { // EPI == 4
        out[(size_t)m*CDIM + n] = g_x2[(size_t)m*CDIM + n] + v;
    }
}

// ---------------- bf16 tensor-core GEMM, 3-stage cp.async pipeline ----------------
// out = Acat[M,Kc] @ Wcat[N,Kc]^T (+bias, epilogue). Kc multiple of 32.
template<int EPI>
__global__ __launch_bounds__(256)
void gemm_bf16(const bf16* __restrict__ A, const bf16* __restrict__ B,
               const float* __restrict__ bias, float* __restrict__ out,
               int Kc, const float* __restrict__ aux0) {
    __shared__ __align__(16) bf16 As[3][128][40];
    __shared__ __align__(16) bf16 Bs[3][64][40];
    const int m0 = blockIdx.x * 128;
    const int n0 = blockIdx.y * 64;
    const int tid = threadIdx.x;
    const int lane = tid & 31, warp = tid >> 5;
    const int warp_m = warp & 3, warp_n = warp >> 2;

    const int arow = tid >> 1, acolv = (tid & 1) * 16;
    const int brow = tid >> 2, bcolv = (tid & 3) * 8;
    const bf16* aptr = A + (size_t)(m0 + arow) * Kc + acolv;
    const bf16* bptr = B + (size_t)(n0 + brow) * Kc + bcolv;

    const int a_r  = warp_m*32 + (lane & 7) + ((lane >> 3) & 1) * 8;
    const int a_c8 = (lane >> 4) * 8;
    const int b_r  = warp_n*32 + (lane >> 4) * 8 + (lane & 7);
    const int b_c8 = ((lane >> 3) & 1) * 8;

    float acc[2][4][4];
#pragma unroll
    for (int i = 0; i < 2; i++)
#pragma unroll
        for (int j = 0; j < 4; j++)
#pragma unroll
            for (int t = 0; t < 4; t++) acc[i][j][t] = 0.f;

    const int nk = Kc >> 5;
    auto issue = [&](int ks) {
        if (ks < nk) {
            int s = ks % 3;
            cp16(&As[s][arow][acolv],     aptr + ks*32);
            cp16(&As[s][arow][acolv + 8], aptr + ks*32 + 8);
            cp16(&Bs[s][brow][bcolv],     bptr + ks*32);
        }
        CP_COMMIT();
    };
    issue(0); issue(1);

    for (int ks = 0; ks < nk; ks++) {
        CP_WAIT1();
        __syncthreads();
        issue(ks + 2);
        const int s = ks % 3;
#pragma unroll
        for (int half = 0; half < 2; half++) {
            u32 afr[2][4], bfr[4][2];
#pragma unroll
            for (int mt = 0; mt < 2; mt++)
                ldm4(afr[mt][0], afr[mt][1], afr[mt][2], afr[mt][3],
                     &As[s][a_r + mt*16][half*16 + a_c8]);
#pragma unroll
            for (int np = 0; np < 2; np++)
                ldm4(bfr[2*np][0], bfr[2*np][1], bfr[2*np+1][0], bfr[2*np+1][1],
                     &Bs[s][b_r + np*16][half*16 + b_c8]);
#pragma unroll
            for (int mt = 0; mt < 2; mt++)
#pragma unroll
                for (int nt = 0; nt < 4; nt++)
                    mma16816(acc[mt][nt], afr[mt], bfr[nt]);
        }
    }
#pragma unroll
    for (int mt = 0; mt < 2; mt++) {
        int mrow = m0 + warp_m*32 + mt*16 + (lane >> 2);
#pragma unroll
        for (int nt = 0; nt < 4; nt++) {
            int ncol = n0 + warp_n*32 + nt*8 + 2*(lane & 3);
            epi_store<EPI>(mrow,     ncol,     acc[mt][nt][0] + bias[ncol],   out, aux0);
            epi_store<EPI>(mrow,     ncol + 1, acc[mt][nt][1] + bias[ncol+1], out, aux0);
            epi_store<EPI>(mrow + 8, ncol,     acc[mt][nt][2] + bias[ncol],   out, aux0);
            epi_store<EPI>(mrow + 8, ncol + 1, acc[mt][nt][3] + bias[ncol+1], out, aux0);
        }
    }
}

// ---------------- bf16 tensor-core 3x3x3 conv, 3-stage cp.async ----------------
// CEPI: 0 = gelu -> g_h1c cat (K=64), 1 = plain fp32 -> g_h2
template<int CEPI>
__global__ __launch_bounds__(256)
void conv_bf16(const bf16* __restrict__ Acat, const bf16* __restrict__ Wcat,
               const float* __restrict__ bias, int Kc, int COUT) {
    __shared__ __align__(16) bf16 As[3][128][40];
    __shared__ __align__(16) bf16 Bs[3][64][40];
    const int l0 = blockIdx.x * 128;
    const int n0 = blockIdx.y * 64;
    const int tid = threadIdx.x;
    const int lane = tid & 31, warp = tid >> 5;
    const int warp_m = warp & 3, warp_n = warp >> 2;

    const int arow = tid >> 1, acolv = (tid & 1) * 16;
    const int l = l0 + arow;
    const int d = l >> 12, hh = (l >> 6) & 63, ww = l & 63;
    const int brow = tid >> 2, bcolv = (tid & 3) * 8;

    const int a_r  = warp_m*32 + (lane & 7) + ((lane >> 3) & 1) * 8;
    const int a_c8 = (lane >> 4) * 8;
    const int b_r  = warp_n*32 + (lane >> 4) * 8 + (lane & 7);
    const int b_c8 = ((lane >> 3) & 1) * 8;

    float acc[2][4][4];
#pragma unroll
    for (int i = 0; i < 2; i++)
#pragma unroll
        for (int j = 0; j < 4; j++)
#pragma unroll
            for (int t = 0; t < 4; t++) acc[i][j][t] = 0.f;

    const int nchunk = Kc >> 5;
    const int nks = 27 * nchunk;

    auto issue = [&](int ks) {
        if (ks < nks) {
            int s = ks % 3;
            int kk = ks / nchunk, c0 = (ks % nchunk) * 32;
            int dd = kk/9 - 1, dh = (kk/3)%3 - 1, dw = kk%3 - 1;
            bool valid = ((unsigned)(d+dd) < 8u) && ((unsigned)(hh+dh) < 64u) && ((unsigned)(ww+dw) < 64u);
            const bf16* p = valid ? (Acat + (size_t)(l + dd*4096 + dh*64 + dw) * Kc + c0 + acolv) : Acat;
            cp16z(&As[s][arow][acolv],     p,     valid);
            cp16z(&As[s][arow][acolv + 8], p + 8, valid);
            cp16(&Bs[s][brow][bcolv],
                 Wcat + ((size_t)kk*COUT + n0 + brow) * Kc + c0 + bcolv);
        }
        CP_COMMIT();
    };
    issue(0); issue(1);

    for (int ks = 0; ks < nks; ks++) {
        CP_WAIT1();
        __syncthreads();
        issue(ks + 2);
        const int s = ks % 3;
#pragma unroll
        for (int half = 0; half < 2; half++) {
            u32 afr[2][4], bfr[4][2];
#pragma unroll
            for (int mt = 0; mt < 2; mt++)
                ldm4(afr[mt][0], afr[mt][1], afr[mt][2], afr[mt][3],
                     &As[s][a_r + mt*16][half*16 + a_c8]);
#pragma unroll
            for (int np = 0; np < 2; np++)
                ldm4(bfr[2*np][0], bfr[2*np][1], bfr[2*np+1][0], bfr[2*np+1][1],
                     &Bs[s][b_r + np*16][half*16 + b_c8]);
#pragma unroll
            for (int mt = 0; mt < 2; mt++)
#pragma unroll
                for (int nt = 0; nt < 4; nt++)
                    mma16816(acc[mt][nt], afr[mt], bfr[nt]);
        }
    }
#pragma unroll
    for (int mt = 0; mt < 2; mt++) {
        int row = warp_m*32 + mt*16 + (lane >> 2);
#pragma unroll
        for (int nt = 0; nt < 4; nt++) {
            int co = n0 + warp_n*32 + nt*8 + 2*(lane & 3);
#pragma unroll
            for (int q = 0; q < 4; q++) {
                int tok = l0 + row + (q >> 1) * 8;
                int c   = co + (q & 1);
                float v = acc[mt][nt][q] + bias[c];
                if (CEPI == 0) store_cat(g_h1c + (size_t)tok * 192, 64, c, gelu_exact(v));
                else           g_h2[(size_t)tok * CDIM + c] = v;
            }
        }
    }
}

// ---------------- global avg pool (stage 1) ----------------
__global__ void pool_kernel(const float* __restrict__ h2, float* __restrict__ partial) {
    int b = blockIdx.x, c = threadIdx.x;
    float s = 0.f;
    const float* base = h2 + (size_t)b * 256 * CDIM + c;
    for (int r = 0; r < 256; r++) s += base[(size_t)r * CDIM];
    partial[b*CDIM + c] = s;
}

// ---------------- channel attention (stage 2) ----------------
__global__ void ca_kernel(const float* __restrict__ partial,
                          const float* __restrict__ ca1w, const float* __restrict__ ca1b,
                          const float* __restrict__ ca2w, const float* __restrict__ ca2b) {
    __shared__ float pooled[CDIM];
    __shared__ float t6[6];
    int c = threadIdx.x;
    float s = 0.f;
    for (int b = 0; b < 128; b++) s += partial[b*CDIM + c];
    pooled[c] = s * (1.f/32768.f);
    __syncthreads();
    if (c < 6) {
        float a = ca1b[c];
        for (int i = 0; i < CDIM; i++) a += pooled[i] * ca1w[c*CDIM + i];
        t6[c] = fmaxf(a, 0.f);
    }
    __syncthreads();
    float a = ca2b[c];
#pragma unroll
    for (int j = 0; j < 6; j++) a += t6[j] * ca2w[c*6 + j];
    g_ca[c] = 1.f / (1.f + __expf(-a));
}

// ---------------- window attention (scalar, proven) + cat epilogue ----------------
__global__ __launch_bounds__(512)
void attn_kernel() {
    extern __shared__ float sm[];
    float* sk = sm;
    float* sv = sm + NTOK*HDD;
    int wi = blockIdx.x / NHD, hh = blockIdx.x % NHD;
    size_t base = ((size_t)(wi*NHD + hh)) * NTOK * HDD;
    int tid = threadIdx.x;
    const float4* k4 = (const float4*)(g_k + base);
    const float4* v4 = (const float4*)(g_v + base);
    for (int i = tid; i < NTOK*HDD/4; i += 512) {
        ((float4*)sk)[i] = k4[i];
        ((float4*)sv)[i] = v4[i];
    }
    __syncthreads();
    const int r = tid;
    float qr[32];
    const float4* q4 = (const float4*)(g_q + base + (size_t)r * HDD);
#pragma unroll
    for (int i = 0; i < 8; i++) {
        float4 t = q4[i];
        qr[4*i] = t.x; qr[4*i+1] = t.y; qr[4*i+2] = t.z; qr[4*i+3] = t.w;
    }
    const float* brow = g_bias + ((size_t)hh*NTOK + r) * NTOK;
    float mmax = -1e30f, lsum = 0.f;
    float o[32];
#pragma unroll
    for (int i = 0; i < 32; i++) o[i] = 0.f;
    for (int j4 = 0; j4 < NTOK; j4 += 4) {
        float4 bq = *(const float4*)&brow[j4];
        float bvv[4] = {bq.x, bq.y, bq.z, bq.w};
#pragma unroll
        for (int jj = 0; jj < 4; jj++) {
            int j = j4 + jj;
            const float4* kr = (const float4*)(sk + j*HDD);
            float s = bvv[jj];
#pragma unroll
            for (int i = 0; i < 8; i++) {
                float4 kv = kr[i];
                s += qr[4*i]*kv.x + qr[4*i+1]*kv.y + qr[4*i+2]*kv.z + qr[4*i+3]*kv.w;
            }
            const float4* vr = (const float4*)(sv + j*HDD);
            if (s <= mmax) {
                float p = __expf(s - mmax);
                lsum += p;
#pragma unroll
                for (int i = 0; i < 8; i++) {
                    float4 vv = vr[i];
                    o[4*i]   += p*vv.x; o[4*i+1] += p*vv.y;
                    o[4*i+2] += p*vv.z; o[4*i+3] += p*vv.w;
                }
            } else {
                float sc = __expf(mmax - s);
                mmax = s;
                lsum = lsum*sc + 1.f;
#pragma unroll
                for (int i = 0; i < 8; i++) {
                    float4 vv = vr[i];
                    o[4*i]   = o[4*i]*sc   + vv.x;
                    o[4*i+1] = o[4*i+1]*sc + vv.y;
                    o[4*i+2] = o[4*i+2]*sc + vv.z;
                    o[4*i+3] = o[4*i+3]*sc + vv.w;
                }
            }
        }
    }
    float inv = 1.f / lsum;
    bf16* dst = g_aoc + (size_t)(wi*NTOK + r) * 576;
#pragma unroll
    for (int i = 0; i < 32; i++)
        store_cat(dst, 192, hh*HDD + i, o[i]*inv);
}

// ---------------- launch ----------------
extern "C" void kernel_launch(void* const* d_in, const int* in_sizes, int n_in,
                              void* d_out, int out_size) {
    const float* x     = (const float*)d_in[0];
    const float* n1g   = (const float*)d_in[1];
    const float* n1b   = (const float*)d_in[2];
    const float* qkvw  = (const float*)d_in[3];
    const float* qkvb  = (const float*)d_in[4];
    const float* rpb   = (const float*)d_in[5];
    const float* projw = (const float*)d_in[6];
    const float* projb = (const float*)d_in[7];
    const float* c1w   = (const float*)d_in[8];
    const float* c1b   = (const float*)d_in[9];
    const float* c2w   = (const float*)d_in[10];
    const float* c2b   = (const float*)d_in[11];
    const float* ca1w  = (const float*)d_in[12];
    const float* ca1b  = (const float*)d_in[13];
    const float* ca2w  = (const float*)d_in[14];
    const float* ca2b  = (const float*)d_in[15];
    const float* n2g   = (const float*)d_in[16];
    const float* n2b   = (const float*)d_in[17];
    const float* fc1w  = (const float*)d_in[18];
    const float* fc1b  = (const float*)d_in[19];
    const float* fc2w  = (const float*)d_in[20];
    const float* fc2b  = (const float*)d_in[21];
    const int*   rpi   = (const int*)d_in[22];
    float* out = (float*)d_out;

    bf16 *p_xnc, *p_aoc, *p_x2nc, *p_h1c, *p_mhc;
    bf16 *p_qkvwc, *p_projwc, *p_fc1wc, *p_fc2wc, *p_w1c, *p_w2c;
    float *p_h2, *p_x2, *p_pp;
    cudaGetSymbolAddress((void**)&p_xnc,    g_xnc);
    cudaGetSymbolAddress((void**)&p_aoc,    g_aoc);
    cudaGetSymbolAddress((void**)&p_x2nc,   g_x2nc);
    cudaGetSymbolAddress((void**)&p_h1c,    g_h1c);
    cudaGetSymbolAddress((void**)&p_mhc,    g_mhc);
    cudaGetSymbolAddress((void**)&p_qkvwc,  g_qkvwc);
    cudaGetSymbolAddress((void**)&p_projwc, g_projwc);
    cudaGetSymbolAddress((void**)&p_fc1wc,  g_fc1wc);
    cudaGetSymbolAddress((void**)&p_fc2wc,  g_fc2wc);
    cudaGetSymbolAddress((void**)&p_w1c,    g_w1c);
    cudaGetSymbolAddress((void**)&p_w2c,    g_w2c);
    cudaGetSymbolAddress((void**)&p_h2,     g_h2);
    cudaGetSymbolAddress((void**)&p_x2,     g_x2);
    cudaGetSymbolAddress((void**)&p_pp,     g_pp);

    cudaFuncSetAttribute(attn_kernel, cudaFuncAttributeMaxDynamicSharedMemorySize,
                         2 * NTOK * HDD * (int)sizeof(float));

    // 1) weight splits + bias gather (small)
    wsplit_dense<<<(576*192 + 255)/256, 256>>>(qkvw, p_qkvwc, 192, 576*192);
    wsplit_dense<<<(192*192 + 255)/256, 256>>>(projw, p_projwc, 192, 192*192);
    wsplit_dense<<<(768*192 + 255)/256, 256>>>(fc1w, p_fc1wc, 192, 768*192);
    wsplit_dense<<<(192*768 + 255)/256, 256>>>(fc2w, p_fc2wc, 768, 192*768);
    wsplit_conv1<<<(64*192*27 + 255)/256, 256>>>(c1w);
    wsplit_conv2<<<(192*64*27 + 255)/256, 256>>>(c2w);
    bias_kernel<<<(NHD*NTOK*NTOK + 255)/256, 256>>>(rpi, rpb);
    // 2) LN1 -> split-cat
    ln_split_kernel<<<4096, dim3(32, 8)>>>(x, n1g, n1b, p_xnc);
    // 3) QKV projection (tensor core) -> window-layout q/k/v
    gemm_bf16<1><<<dim3(256, 9), 256>>>(p_xnc, p_qkvwc, qkvb, nullptr, 576, nullptr);
    // 4) conv branch (tensor core)
    conv_bf16<0><<<dim3(256, 1), 256>>>(p_xnc, p_w1c, c1b, 576, 64);
    conv_bf16<1><<<dim3(256, 3), 256>>>(p_h1c, p_w2c, c2b, 192, 192);
    pool_kernel<<<128, CDIM>>>(p_h2, p_pp);
    ca_kernel<<<1, CDIM>>>(p_pp, ca1w, ca1b, ca2w, ca2b);
    // 5) window attention (scalar) -> split-cat
    attn_kernel<<<NWIN * NHD, 512, 2 * NTOK * HDD * (int)sizeof(float)>>>();
    // 6) proj + window reverse + residual + conv*0.01 -> g_x2
    gemm_bf16<2><<<dim3(256, 3), 256>>>(p_aoc, p_projwc, projb, nullptr, 576, x);
    // 7) LN2 + MLP
    ln_split_kernel<<<4096, dim3(32, 8)>>>(p_x2, n2g, n2b, p_x2nc);
    gemm_bf16<3><<<dim3(256, 12), 256>>>(p_x2nc, p_fc1wc, fc1b, nullptr, 576, nullptr);
    gemm_bf16<4><<<dim3(256, 3), 256>>>(p_mhc, p_fc2wc, fc2b, out, 2304, nullptr);
}

// round 6
// speedup vs baseline: 3.7625x; 1.2543x over previous
#include <cuda_runtime.h>
#include <cuda_bf16.h>
#include <math.h>

// ---------------- problem constants ----------------
#define LTOK 32768      // B * D*H*W
#define CDIM 192
#define NWIN 64
#define NHD  6
#define NTOK 512
#define HDD  32
#define NWH  (NWIN*NHD)   // 384

typedef unsigned int u32;
typedef __nv_bfloat16 bf16;

// ---------------- device scratch (static, allocation-free) ----------------
__device__ float g_h2[LTOK * CDIM];
__device__ float g_x2[LTOK * CDIM];
__device__ float g_bias[NHD * NTOK * NTOK];
__device__ float g_pp[128 * CDIM];
__device__ float g_ca[CDIM];
// attention operands (bf16 split)
__device__ bf16 g_qc [NWH * NTOK * 96];   // q cat [hi|hi|lo], scaled
__device__ bf16 g_kc [NWH * NTOK * 96];   // k cat [hi|lo|hi]
__device__ bf16 g_vth[NWH * HDD * NTOK];  // V hi transposed [wh][d][tok]
__device__ bf16 g_vtl[NWH * HDD * NTOK];  // V lo transposed
// bf16 split-cat activations: [hi | hi | lo], row stride 3K
__device__ bf16 g_xnc [LTOK * 576];      // K=192
__device__ bf16 g_aoc [LTOK * 576];      // K=192 (attention out)
__device__ bf16 g_x2nc[LTOK * 576];      // K=192
__device__ bf16 g_h1c [LTOK * 192];      // K=64
__device__ bf16 g_mhc [(size_t)LTOK * 2304];  // K=768
// bf16 split-cat weights: [hi | lo | hi], row stride 3K
__device__ bf16 g_qkvwc[576 * 576];
__device__ bf16 g_projwc[192 * 576];
__device__ bf16 g_fc1wc[768 * 576];
__device__ bf16 g_fc2wc[192 * 2304];
__device__ bf16 g_w1c[27 * 64 * 576];    // [kk][co][3*192]
__device__ bf16 g_w2c[27 * 192 * 192];   // [kk][co][3*64]

__device__ __forceinline__ float gelu_exact(float x) {
    return 0.5f * x * (1.0f + erff(x * 0.70710678118654752440f));
}

// write activation split-cat: [hi, hi, lo]
__device__ __forceinline__ void store_cat(bf16* __restrict__ rowp, int K, int k, float v) {
    bf16 h = __float2bfloat16(v);
    bf16 l = __float2bfloat16(v - __bfloat162float(h));
    rowp[k] = h; rowp[K + k] = h; rowp[2*K + k] = l;
}
__device__ __forceinline__ u32 packbf2(float a, float b) {
    __nv_bfloat162 t = __floats2bfloat162_rn(a, b);
    return *(u32*)&t;
}

// ---------------- mma / ldmatrix / cp.async helpers ----------------
__device__ __forceinline__ void ldm4(u32& r0, u32& r1, u32& r2, u32& r3, const bf16* p) {
    u32 addr = (u32)__cvta_generic_to_shared(p);
    asm volatile("ldmatrix.sync.aligned.m8n8.x4.shared.b16 {%0,%1,%2,%3},[%4];"
                 : "=r"(r0), "=r"(r1), "=r"(r2), "=r"(r3) : "r"(addr));
}
__device__ __forceinline__ void mma16816(float* c, const u32* a, const u32* b) {
    asm volatile(
        "mma.sync.aligned.m16n8k16.row.col.f32.bf16.bf16.f32 "
        "{%0,%1,%2,%3},{%4,%5,%6,%7},{%8,%9},{%0,%1,%2,%3};"
        : "+f"(c[0]), "+f"(c[1]), "+f"(c[2]), "+f"(c[3])
        : "r"(a[0]), "r"(a[1]), "r"(a[2]), "r"(a[3]), "r"(b[0]), "r"(b[1]));
}
__device__ __forceinline__ void cp16(bf16* dst, const bf16* src) {
    u32 d = (u32)__cvta_generic_to_shared(dst);
    asm volatile("cp.async.cg.shared.global [%0],[%1],16;" :: "r"(d), "l"(src));
}
__device__ __forceinline__ void cp16z(bf16* dst, const bf16* src, bool v) {
    u32 d = (u32)__cvta_generic_to_shared(dst);
    int sz = v ? 16 : 0;
    asm volatile("cp.async.cg.shared.global [%0],[%1],16,%2;" :: "r"(d), "l"(src), "r"(sz));
}
#define CP_COMMIT() asm volatile("cp.async.commit_group;")
#define CP_WAIT1()  asm volatile("cp.async.wait_group 1;")

// ---------------- LayerNorm + split-cat write ----------------
__global__ void ln_split_kernel(const float* __restrict__ x, const float* __restrict__ g,
                                const float* __restrict__ b, bf16* __restrict__ dst) {
    int row  = blockIdx.x * blockDim.y + threadIdx.y;
    int lane = threadIdx.x;
    const float* xr = x + (size_t)row * CDIM;
    float v[6]; float s = 0.f, ss = 0.f;
#pragma unroll
    for (int i = 0; i < 6; i++) { v[i] = xr[lane + 32*i]; s += v[i]; ss += v[i]*v[i]; }
#pragma unroll
    for (int o = 16; o > 0; o >>= 1) {
        s  += __shfl_xor_sync(0xffffffffu, s, o);
        ss += __shfl_xor_sync(0xffffffffu, ss, o);
    }
    float mean = s * (1.f/192.f);
    float var  = ss * (1.f/192.f) - mean*mean;
    float rstd = rsqrtf(var + 1e-5f);
    bf16* orow = dst + (size_t)row * 576;
#pragma unroll
    for (int i = 0; i < 6; i++) {
        int c = lane + 32*i;
        store_cat(orow, 192, c, (v[i]-mean)*rstd*g[c] + b[c]);
    }
}

// ---------------- weight split kernels ----------------
__global__ void wsplit_dense(const float* __restrict__ src, bf16* __restrict__ dst,
                             int K, int total) {
    int idx = blockIdx.x * 256 + threadIdx.x;
    if (idx >= total) return;
    int n = idx / K, k = idx % K;
    float v = src[idx];
    bf16 h = __float2bfloat16(v);
    bf16 l = __float2bfloat16(v - __bfloat162float(h));
    bf16* rowp = dst + (size_t)n * 3 * K;
    rowp[k] = h; rowp[K + k] = l; rowp[2*K + k] = h;
}
__global__ void wsplit_conv1(const float* __restrict__ src) {
    int idx = blockIdx.x * 256 + threadIdx.x;
    if (idx >= 64*192*27) return;
    int co = idx / (192*27), ci = (idx / 27) % 192, kk = idx % 27;
    float v = src[idx];
    bf16 h = __float2bfloat16(v);
    bf16 l = __float2bfloat16(v - __bfloat162float(h));
    bf16* rowp = g_w1c + ((size_t)kk*64 + co) * 576;
    rowp[ci] = h; rowp[192 + ci] = l; rowp[384 + ci] = h;
}
__global__ void wsplit_conv2(const float* __restrict__ src) {
    int idx = blockIdx.x * 256 + threadIdx.x;
    if (idx >= 192*64*27) return;
    int co = idx / (64*27), ci = (idx / 27) % 64, kk = idx % 27;
    float v = src[idx];
    bf16 h = __float2bfloat16(v);
    bf16 l = __float2bfloat16(v - __bfloat162float(h));
    bf16* rowp = g_w2c + ((size_t)kk*192 + co) * 192;
    rowp[ci] = h; rowp[64 + ci] = l; rowp[128 + ci] = h;
}

// ---------------- relative-position bias gather ----------------
__global__ void bias_kernel(const int* __restrict__ rpi, const float* __restrict__ rpb) {
    int idx = blockIdx.x * 256 + threadIdx.x;
    if (idx >= NHD * NTOK * NTOK) return;
    int h  = idx / (NTOK*NTOK);
    int nm = idx % (NTOK*NTOK);
    g_bias[idx] = rpb[rpi[nm]*NHD + h];
}

// ---------------- epilogue dispatch ----------------
// EPI: 1 qkv-scatter(bf16 split), 2 proj+residual, 3 fc1 gelu->cat, 4 final add
template<int EPI>
__device__ __forceinline__ void epi_store(int m, int n, float v,
                                          float* __restrict__ out,
                                          const float* __restrict__ aux0) {
    if (EPI == 1) {
        int which = n / 192, c = n % 192;
        int head = c >> 5, hd = c & 31;
        int d = m >> 12, h = (m >> 6) & 63, w = m & 63;
        int wi = ((h >> 3) << 3) | (w >> 3);
        int nt = (d << 6) | ((h & 7) << 3) | (w & 7);
        int wh = wi*NHD + head;
        if (which == 0) {
            float q = v * 0.17677669529663687f; // HD^-0.5
            bf16 hi = __float2bfloat16(q);
            bf16 lo = __float2bfloat16(q - __bfloat162float(hi));
            bf16* rp = g_qc + ((size_t)wh*NTOK + nt) * 96;
            rp[hd] = hi; rp[32 + hd] = hi; rp[64 + hd] = lo;   // [hi|hi|lo]
        } else if (which == 1) {
            bf16 hi = __float2bfloat16(v);
            bf16 lo = __float2bfloat16(v - __bfloat162float(hi));
            bf16* rp = g_kc + ((size_t)wh*NTOK + nt) * 96;
            rp[hd] = hi; rp[32 + hd] = lo; rp[64 + hd] = hi;   // [hi|lo|hi]
        } else {
            bf16 hi = __float2bfloat16(v);
            bf16 lo = __float2bfloat16(v - __bfloat162float(hi));
            size_t o = ((size_t)wh*HDD + hd)*NTOK + nt;
            g_vth[o] = hi; g_vtl[o] = lo;
        }
    } else if (EPI == 2) {
        int wi = m >> 9, nt = m & 511;
        int d = nt >> 6;
        int h = ((wi >> 3) << 3) | ((nt >> 3) & 7);
        int w = ((wi & 7) << 3) | (nt & 7);
        size_t l = ((size_t)d << 12) | (h << 6) | w;
        size_t o = l*CDIM + n;
        g_x2[o] = aux0[o] + v + g_h2[o] * g_ca[n] * 0.01f;
    } else if (EPI == 3) {
        store_cat(g_mhc + (size_t)m * 2304, 768, n, gelu_exact(v));
    } else { // EPI == 4
        out[(size_t)m*CDIM + n] = g_x2[(size_t)m*CDIM + n] + v;
    }
}

// ---------------- bf16 tensor-core GEMM, 3-stage cp.async pipeline ----------------
template<int EPI>
__global__ __launch_bounds__(256)
void gemm_bf16(const bf16* __restrict__ A, const bf16* __restrict__ B,
               const float* __restrict__ bias, float* __restrict__ out,
               int Kc, const float* __restrict__ aux0) {
    __shared__ __align__(16) bf16 As[3][128][40];
    __shared__ __align__(16) bf16 Bs[3][64][40];
    const int m0 = blockIdx.x * 128;
    const int n0 = blockIdx.y * 64;
    const int tid = threadIdx.x;
    const int lane = tid & 31, warp = tid >> 5;
    const int warp_m = warp & 3, warp_n = warp >> 2;

    const int arow = tid >> 1, acolv = (tid & 1) * 16;
    const int brow = tid >> 2, bcolv = (tid & 3) * 8;
    const bf16* aptr = A + (size_t)(m0 + arow) * Kc + acolv;
    const bf16* bptr = B + (size_t)(n0 + brow) * Kc + bcolv;

    const int a_r  = warp_m*32 + (lane & 7) + ((lane >> 3) & 1) * 8;
    const int a_c8 = (lane >> 4) * 8;
    const int b_r  = warp_n*32 + (lane >> 4) * 8 + (lane & 7);
    const int b_c8 = ((lane >> 3) & 1) * 8;

    float acc[2][4][4];
#pragma unroll
    for (int i = 0; i < 2; i++)
#pragma unroll
        for (int j = 0; j < 4; j++)
#pragma unroll
            for (int t = 0; t < 4; t++) acc[i][j][t] = 0.f;

    const int nk = Kc >> 5;
    auto issue = [&](int ks) {
        if (ks < nk) {
            int s = ks % 3;
            cp16(&As[s][arow][acolv],     aptr + ks*32);
            cp16(&As[s][arow][acolv + 8], aptr + ks*32 + 8);
            cp16(&Bs[s][brow][bcolv],     bptr + ks*32);
        }
        CP_COMMIT();
    };
    issue(0); issue(1);

    for (int ks = 0; ks < nk; ks++) {
        CP_WAIT1();
        __syncthreads();
        issue(ks + 2);
        const int s = ks % 3;
#pragma unroll
        for (int half = 0; half < 2; half++) {
            u32 afr[2][4], bfr[4][2];
#pragma unroll
            for (int mt = 0; mt < 2; mt++)
                ldm4(afr[mt][0], afr[mt][1], afr[mt][2], afr[mt][3],
                     &As[s][a_r + mt*16][half*16 + a_c8]);
#pragma unroll
            for (int np = 0; np < 2; np++)
                ldm4(bfr[2*np][0], bfr[2*np][1], bfr[2*np+1][0], bfr[2*np+1][1],
                     &Bs[s][b_r + np*16][half*16 + b_c8]);
#pragma unroll
            for (int mt = 0; mt < 2; mt++)
#pragma unroll
                for (int nt = 0; nt < 4; nt++)
                    mma16816(acc[mt][nt], afr[mt], bfr[nt]);
        }
    }
#pragma unroll
    for (int mt = 0; mt < 2; mt++) {
        int mrow = m0 + warp_m*32 + mt*16 + (lane >> 2);
#pragma unroll
        for (int nt = 0; nt < 4; nt++) {
            int ncol = n0 + warp_n*32 + nt*8 + 2*(lane & 3);
            epi_store<EPI>(mrow,     ncol,     acc[mt][nt][0] + bias[ncol],   out, aux0);
            epi_store<EPI>(mrow,     ncol + 1, acc[mt][nt][1] + bias[ncol+1], out, aux0);
            epi_store<EPI>(mrow + 8, ncol,     acc[mt][nt][2] + bias[ncol],   out, aux0);
            epi_store<EPI>(mrow + 8, ncol + 1, acc[mt][nt][3] + bias[ncol+1], out, aux0);
        }
    }
}

// ---------------- bf16 tensor-core 3x3x3 conv, 3-stage cp.async ----------------
template<int CEPI>
__global__ __launch_bounds__(256)
void conv_bf16(const bf16* __restrict__ Acat, const bf16* __restrict__ Wcat,
               const float* __restrict__ bias, int Kc, int COUT) {
    __shared__ __align__(16) bf16 As[3][128][40];
    __shared__ __align__(16) bf16 Bs[3][64][40];
    const int l0 = blockIdx.x * 128;
    const int n0 = blockIdx.y * 64;
    const int tid = threadIdx.x;
    const int lane = tid & 31, warp = tid >> 5;
    const int warp_m = warp & 3, warp_n = warp >> 2;

    const int arow = tid >> 1, acolv = (tid & 1) * 16;
    const int l = l0 + arow;
    const int d = l >> 12, hh = (l >> 6) & 63, ww = l & 63;
    const int brow = tid >> 2, bcolv = (tid & 3) * 8;

    const int a_r  = warp_m*32 + (lane & 7) + ((lane >> 3) & 1) * 8;
    const int a_c8 = (lane >> 4) * 8;
    const int b_r  = warp_n*32 + (lane >> 4) * 8 + (lane & 7);
    const int b_c8 = ((lane >> 3) & 1) * 8;

    float acc[2][4][4];
#pragma unroll
    for (int i = 0; i < 2; i++)
#pragma unroll
        for (int j = 0; j < 4; j++)
#pragma unroll
            for (int t = 0; t < 4; t++) acc[i][j][t] = 0.f;

    const int nchunk = Kc >> 5;
    const int nks = 27 * nchunk;

    auto issue = [&](int ks) {
        if (ks < nks) {
            int s = ks % 3;
            int kk = ks / nchunk, c0 = (ks % nchunk) * 32;
            int dd = kk/9 - 1, dh = (kk/3)%3 - 1, dw = kk%3 - 1;
            bool valid = ((unsigned)(d+dd) < 8u) && ((unsigned)(hh+dh) < 64u) && ((unsigned)(ww+dw) < 64u);
            const bf16* p = valid ? (Acat + (size_t)(l + dd*4096 + dh*64 + dw) * Kc + c0 + acolv) : Acat;
            cp16z(&As[s][arow][acolv],     p,     valid);
            cp16z(&As[s][arow][acolv + 8], p + 8, valid);
            cp16(&Bs[s][brow][bcolv],
                 Wcat + ((size_t)kk*COUT + n0 + brow) * Kc + c0 + bcolv);
        }
        CP_COMMIT();
    };
    issue(0); issue(1);

    for (int ks = 0; ks < nks; ks++) {
        CP_WAIT1();
        __syncthreads();
        issue(ks + 2);
        const int s = ks % 3;
#pragma unroll
        for (int half = 0; half < 2; half++) {
            u32 afr[2][4], bfr[4][2];
#pragma unroll
            for (int mt = 0; mt < 2; mt++)
                ldm4(afr[mt][0], afr[mt][1], afr[mt][2], afr[mt][3],
                     &As[s][a_r + mt*16][half*16 + a_c8]);
#pragma unroll
            for (int np = 0; np < 2; np++)
                ldm4(bfr[2*np][0], bfr[2*np][1], bfr[2*np+1][0], bfr[2*np+1][1],
                     &Bs[s][b_r + np*16][half*16 + b_c8]);
#pragma unroll
            for (int mt = 0; mt < 2; mt++)
#pragma unroll
                for (int nt = 0; nt < 4; nt++)
                    mma16816(acc[mt][nt], afr[mt], bfr[nt]);
        }
    }
#pragma unroll
    for (int mt = 0; mt < 2; mt++) {
        int row = warp_m*32 + mt*16 + (lane >> 2);
#pragma unroll
        for (int nt = 0; nt < 4; nt++) {
            int co = n0 + warp_n*32 + nt*8 + 2*(lane & 3);
#pragma unroll
            for (int q = 0; q < 4; q++) {
                int tok = l0 + row + (q >> 1) * 8;
                int c   = co + (q & 1);
                float v = acc[mt][nt][q] + bias[c];
                if (CEPI == 0) store_cat(g_h1c + (size_t)tok * 192, 64, c, gelu_exact(v));
                else           g_h2[(size_t)tok * CDIM + c] = v;
            }
        }
    }
}

// ---------------- global avg pool (stage 1) ----------------
__global__ void pool_kernel(const float* __restrict__ h2, float* __restrict__ partial) {
    int b = blockIdx.x, c = threadIdx.x;
    float s = 0.f;
    const float* base = h2 + (size_t)b * 256 * CDIM + c;
    for (int r = 0; r < 256; r++) s += base[(size_t)r * CDIM];
    partial[b*CDIM + c] = s;
}

// ---------------- channel attention (stage 2) ----------------
__global__ void ca_kernel(const float* __restrict__ partial,
                          const float* __restrict__ ca1w, const float* __restrict__ ca1b,
                          const float* __restrict__ ca2w, const float* __restrict__ ca2b) {
    __shared__ float pooled[CDIM];
    __shared__ float t6[6];
    int c = threadIdx.x;
    float s = 0.f;
    for (int b = 0; b < 128; b++) s += partial[b*CDIM + c];
    pooled[c] = s * (1.f/32768.f);
    __syncthreads();
    if (c < 6) {
        float a = ca1b[c];
        for (int i = 0; i < CDIM; i++) a += pooled[i] * ca1w[c*CDIM + i];
        t6[c] = fmaxf(a, 0.f);
    }
    __syncthreads();
    float a = ca2b[c];
#pragma unroll
    for (int j = 0; j < 6; j++) a += t6[j] * ca2w[c*6 + j];
    g_ca[c] = 1.f / (1.f + __expf(-a));
}

// ---------------- flash attention (mma.sync, split-precision) ----------------
// grid (4, 384): blockIdx.x = 128-query tile, blockIdx.y = wh. 256 threads.
#define QS_SZ  (128*104)
#define KS_SZ  (128*104)
#define VS_SZ  (32*136)
__global__ __launch_bounds__(256)
void fa_kernel() {
    extern __shared__ __align__(16) bf16 sm[];
    bf16* Qs  = sm;                        // [128][104]
    bf16* Ks  = Qs + QS_SZ;                // [3][128][104]
    bf16* Vhs = Ks + 3*KS_SZ;              // [3][32][136]
    bf16* Vls = Vhs + 3*VS_SZ;             // [3][32][136]

    const int wh = blockIdx.y, qt = blockIdx.x;
    const int wi = wh / NHD, hh = wh % NHD;
    const int tid = threadIdx.x, lane = tid & 31, warp = tid >> 5;

    const bf16* qg  = g_qc  + ((size_t)wh*NTOK + qt*128) * 96;
    const bf16* kg  = g_kc  + (size_t)wh*NTOK*96;
    const bf16* vhg = g_vth + (size_t)wh*HDD*NTOK;
    const bf16* vlg = g_vtl + (size_t)wh*HDD*NTOK;

    // Q + tile0 (group 0)
    for (int c = tid; c < 1536; c += 256)
        cp16(&Qs[(c/12)*104 + (c%12)*8], qg + (c/12)*96 + (c%12)*8);
    auto issue_tile = [&](int j) {
        if (j < 4) {
            bf16* ks = Ks + (j % 3) * KS_SZ;
            bf16* vh = Vhs + (j % 3) * VS_SZ;
            bf16* vl = Vls + (j % 3) * VS_SZ;
            const bf16* kt = kg + j*128*96;
            for (int c = tid; c < 1536; c += 256)
                cp16(&ks[(c/12)*104 + (c%12)*8], kt + (c/12)*96 + (c%12)*8);
            for (int c = tid; c < 512; c += 256) {
                int d = c >> 4, o = (c & 15) * 8;
                cp16(&vh[d*136 + o], vhg + d*NTOK + j*128 + o);
                cp16(&vl[d*136 + o], vlg + d*NTOK + j*128 + o);
            }
        }
        CP_COMMIT();
    };
    issue_tile(0);   // group 0 includes Q
    issue_tile(1);   // group 1

    // fragment row/col addressing
    const int a_r  = warp*16 + (lane & 7) + ((lane >> 3) & 1) * 8;
    const int a_c8 = (lane >> 4) * 8;
    const int b_rr = (lane >> 4) * 8 + (lane & 7);
    const int b_c8 = ((lane >> 3) & 1) * 8;

    u32 qfr[6][4];
    float o[4][4];
#pragma unroll
    for (int i = 0; i < 4; i++)
#pragma unroll
        for (int j = 0; j < 4; j++) o[i][j] = 0.f;
    float m0 = -1e30f, m1 = -1e30f, l0 = 0.f, l1 = 0.f;

    const int nq = qt*128 + warp*16 + (lane >> 2);
    const float* bias_base = g_bias + ((size_t)hh*NTOK + nq)*NTOK + 2*(lane & 3);

    for (int j = 0; j < 4; j++) {
        CP_WAIT1();
        __syncthreads();
        if (j == 0) {
#pragma unroll
            for (int ks = 0; ks < 6; ks++)
                ldm4(qfr[ks][0], qfr[ks][1], qfr[ks][2], qfr[ks][3],
                     &Qs[a_r*104 + ks*16 + a_c8]);
        }
        issue_tile(j + 2);
        const bf16* ks_s = Ks + (j % 3) * KS_SZ;
        const bf16* vh_s = Vhs + (j % 3) * VS_SZ;
        const bf16* vl_s = Vls + (j % 3) * VS_SZ;

        // ---- S = Qcat @ Kcat^T  (16 n-tiles of 8 keys) ----
        float sf[16][4];
#pragma unroll
        for (int nt = 0; nt < 16; nt++)
#pragma unroll
            for (int q = 0; q < 4; q++) sf[nt][q] = 0.f;
#pragma unroll
        for (int ks = 0; ks < 6; ks++)
#pragma unroll
            for (int pr = 0; pr < 8; pr++) {
                u32 b[4];
                ldm4(b[0], b[1], b[2], b[3],
                     &ks_s[(pr*16 + b_rr)*104 + ks*16 + b_c8]);
                mma16816(sf[2*pr],     qfr[ks], b);
                mma16816(sf[2*pr + 1], qfr[ks], b + 2);
            }
        // ---- bias ----
        const float* bp = bias_base + j*128;
#pragma unroll
        for (int nt = 0; nt < 16; nt++) {
            float2 b0 = *(const float2*)(bp + nt*8);
            float2 b1 = *(const float2*)(bp + 8*NTOK + nt*8);
            sf[nt][0] += b0.x; sf[nt][1] += b0.y;
            sf[nt][2] += b1.x; sf[nt][3] += b1.y;
        }
        // ---- online softmax ----
        float mx0 = -1e30f, mx1 = -1e30f;
#pragma unroll
        for (int nt = 0; nt < 16; nt++) {
            mx0 = fmaxf(mx0, fmaxf(sf[nt][0], sf[nt][1]));
            mx1 = fmaxf(mx1, fmaxf(sf[nt][2], sf[nt][3]));
        }
        mx0 = fmaxf(mx0, __shfl_xor_sync(0xffffffffu, mx0, 1));
        mx0 = fmaxf(mx0, __shfl_xor_sync(0xffffffffu, mx0, 2));
        mx1 = fmaxf(mx1, __shfl_xor_sync(0xffffffffu, mx1, 1));
        mx1 = fmaxf(mx1, __shfl_xor_sync(0xffffffffu, mx1, 2));
        float mn0 = fmaxf(m0, mx0), mn1 = fmaxf(m1, mx1);
        float sc0 = __expf(m0 - mn0), sc1 = __expf(m1 - mn1);
        m0 = mn0; m1 = mn1;
        float rs0 = 0.f, rs1 = 0.f;
#pragma unroll
        for (int nt = 0; nt < 16; nt++) {
            sf[nt][0] = __expf(sf[nt][0] - mn0); rs0 += sf[nt][0];
            sf[nt][1] = __expf(sf[nt][1] - mn0); rs0 += sf[nt][1];
            sf[nt][2] = __expf(sf[nt][2] - mn1); rs1 += sf[nt][2];
            sf[nt][3] = __expf(sf[nt][3] - mn1); rs1 += sf[nt][3];
        }
        rs0 += __shfl_xor_sync(0xffffffffu, rs0, 1);
        rs0 += __shfl_xor_sync(0xffffffffu, rs0, 2);
        rs1 += __shfl_xor_sync(0xffffffffu, rs1, 1);
        rs1 += __shfl_xor_sync(0xffffffffu, rs1, 2);
        l0 = l0*sc0 + rs0; l1 = l1*sc1 + rs1;
#pragma unroll
        for (int dt = 0; dt < 4; dt++) {
            o[dt][0] *= sc0; o[dt][1] *= sc0;
            o[dt][2] *= sc1; o[dt][3] *= sc1;
        }
        // ---- PV: o += Phi*Vhi + Phi*Vlo + Plo*Vhi ----
#pragma unroll
        for (int kt = 0; kt < 8; kt++) {
            float p00 = sf[2*kt][0],   p01 = sf[2*kt][1],   p02 = sf[2*kt][2],   p03 = sf[2*kt][3];
            float p10 = sf[2*kt+1][0], p11 = sf[2*kt+1][1], p12 = sf[2*kt+1][2], p13 = sf[2*kt+1][3];
            u32 phi[4], plo[4];
            {
                float h00 = __bfloat162float(__float2bfloat16(p00));
                float h01 = __bfloat162float(__float2bfloat16(p01));
                float h02 = __bfloat162float(__float2bfloat16(p02));
                float h03 = __bfloat162float(__float2bfloat16(p03));
                float h10 = __bfloat162float(__float2bfloat16(p10));
                float h11 = __bfloat162float(__float2bfloat16(p11));
                float h12 = __bfloat162float(__float2bfloat16(p12));
                float h13 = __bfloat162float(__float2bfloat16(p13));
                phi[0] = packbf2(h00, h01); phi[1] = packbf2(h02, h03);
                phi[2] = packbf2(h10, h11); phi[3] = packbf2(h12, h13);
                plo[0] = packbf2(p00 - h00, p01 - h01); plo[1] = packbf2(p02 - h02, p03 - h03);
                plo[2] = packbf2(p10 - h10, p11 - h11); plo[3] = packbf2(p12 - h12, p13 - h13);
            }
            u32 vhf[8], vlf[8];
            ldm4(vhf[0], vhf[1], vhf[2], vhf[3], &vh_s[b_rr*136 + kt*16 + b_c8]);
            ldm4(vhf[4], vhf[5], vhf[6], vhf[7], &vh_s[(16 + b_rr)*136 + kt*16 + b_c8]);
            ldm4(vlf[0], vlf[1], vlf[2], vlf[3], &vl_s[b_rr*136 + kt*16 + b_c8]);
            ldm4(vlf[4], vlf[5], vlf[6], vlf[7], &vl_s[(16 + b_rr)*136 + kt*16 + b_c8]);
#pragma unroll
            for (int dt = 0; dt < 4; dt++) {
                mma16816(o[dt], phi, &vhf[2*dt]);
                mma16816(o[dt], phi, &vlf[2*dt]);
                mma16816(o[dt], plo, &vhf[2*dt]);
            }
        }
    }
    // ---- normalize + write split-cat attention output ----
    float il0 = 1.f / l0, il1 = 1.f / l1;
    int row = wi*NTOK + qt*128 + warp*16 + (lane >> 2);
    bf16* dst0 = g_aoc + (size_t)row * 576;
    bf16* dst1 = dst0 + (size_t)8 * 576;
#pragma unroll
    for (int dt = 0; dt < 4; dt++) {
        int c = hh*HDD + dt*8 + 2*(lane & 3);
        store_cat(dst0, 192, c,     o[dt][0]*il0);
        store_cat(dst0, 192, c + 1, o[dt][1]*il0);
        store_cat(dst1, 192, c,     o[dt][2]*il1);
        store_cat(dst1, 192, c + 1, o[dt][3]*il1);
    }
}

// ---------------- launch ----------------
extern "C" void kernel_launch(void* const* d_in, const int* in_sizes, int n_in,
                              void* d_out, int out_size) {
    const float* x     = (const float*)d_in[0];
    const float* n1g   = (const float*)d_in[1];
    const float* n1b   = (const float*)d_in[2];
    const float* qkvw  = (const float*)d_in[3];
    const float* qkvb  = (const float*)d_in[4];
    const float* rpb   = (const float*)d_in[5];
    const float* projw = (const float*)d_in[6];
    const float* projb = (const float*)d_in[7];
    const float* c1w   = (const float*)d_in[8];
    const float* c1b   = (const float*)d_in[9];
    const float* c2w   = (const float*)d_in[10];
    const float* c2b   = (const float*)d_in[11];
    const float* ca1w  = (const float*)d_in[12];
    const float* ca1b  = (const float*)d_in[13];
    const float* ca2w  = (const float*)d_in[14];
    const float* ca2b  = (const float*)d_in[15];
    const float* n2g   = (const float*)d_in[16];
    const float* n2b   = (const float*)d_in[17];
    const float* fc1w  = (const float*)d_in[18];
    const float* fc1b  = (const float*)d_in[19];
    const float* fc2w  = (const float*)d_in[20];
    const float* fc2b  = (const float*)d_in[21];
    const int*   rpi   = (const int*)d_in[22];
    float* out = (float*)d_out;

    bf16 *p_xnc, *p_aoc, *p_x2nc, *p_h1c, *p_mhc;
    bf16 *p_qkvwc, *p_projwc, *p_fc1wc, *p_fc2wc, *p_w1c, *p_w2c;
    float *p_h2, *p_x2, *p_pp;
    cudaGetSymbolAddress((void**)&p_xnc,    g_xnc);
    cudaGetSymbolAddress((void**)&p_aoc,    g_aoc);
    cudaGetSymbolAddress((void**)&p_x2nc,   g_x2nc);
    cudaGetSymbolAddress((void**)&p_h1c,    g_h1c);
    cudaGetSymbolAddress((void**)&p_mhc,    g_mhc);
    cudaGetSymbolAddress((void**)&p_qkvwc,  g_qkvwc);
    cudaGetSymbolAddress((void**)&p_projwc, g_projwc);
    cudaGetSymbolAddress((void**)&p_fc1wc,  g_fc1wc);
    cudaGetSymbolAddress((void**)&p_fc2wc,  g_fc2wc);
    cudaGetSymbolAddress((void**)&p_w1c,    g_w1c);
    cudaGetSymbolAddress((void**)&p_w2c,    g_w2c);
    cudaGetSymbolAddress((void**)&p_h2,     g_h2);
    cudaGetSymbolAddress((void**)&p_x2,     g_x2);
    cudaGetSymbolAddress((void**)&p_pp,     g_pp);

    const int fa_smem = (QS_SZ + 3*KS_SZ + 3*VS_SZ*2) * (int)sizeof(bf16);
    cudaFuncSetAttribute(fa_kernel, cudaFuncAttributeMaxDynamicSharedMemorySize, fa_smem);

    // 1) weight splits + bias gather (small)
    wsplit_dense<<<(576*192 + 255)/256, 256>>>(qkvw, p_qkvwc, 192, 576*192);
    wsplit_dense<<<(192*192 + 255)/256, 256>>>(projw, p_projwc, 192, 192*192);
    wsplit_dense<<<(768*192 + 255)/256, 256>>>(fc1w, p_fc1wc, 192, 768*192);
    wsplit_dense<<<(192*768 + 255)/256, 256>>>(fc2w, p_fc2wc, 768, 192*768);
    wsplit_conv1<<<(64*192*27 + 255)/256, 256>>>(c1w);
    wsplit_conv2<<<(192*64*27 + 255)/256, 256>>>(c2w);
    bias_kernel<<<(NHD*NTOK*NTOK + 255)/256, 256>>>(rpi, rpb);
    // 2) LN1 -> split-cat
    ln_split_kernel<<<4096, dim3(32, 8)>>>(x, n1g, n1b, p_xnc);
    // 3) QKV projection (tensor core) -> split attention operands
    gemm_bf16<1><<<dim3(256, 9), 256>>>(p_xnc, p_qkvwc, qkvb, nullptr, 576, nullptr);
    // 4) conv branch (tensor core)
    conv_bf16<0><<<dim3(256, 1), 256>>>(p_xnc, p_w1c, c1b, 576, 64);
    conv_bf16<1><<<dim3(256, 3), 256>>>(p_h1c, p_w2c, c2b, 192, 192);
    pool_kernel<<<128, CDIM>>>(p_h2, p_pp);
    ca_kernel<<<1, CDIM>>>(p_pp, ca1w, ca1b, ca2w, ca2b);
    // 5) flash attention (tensor core) -> split-cat
    fa_kernel<<<dim3(4, NWH), 256, fa_smem>>>();
    // 6) proj + window reverse + residual + conv*0.01 -> g_x2
    gemm_bf16<2><<<dim3(256, 3), 256>>>(p_aoc, p_projwc, projb, nullptr, 576, x);
    // 7) LN2 + MLP
    ln_split_kernel<<<4096, dim3(32, 8)>>>(p_x2, n2g, n2b, p_x2nc);
    gemm_bf16<3><<<dim3(256, 12), 256>>>(p_x2nc, p_fc1wc, fc1b, nullptr, 576, nullptr);
    gemm_bf16<4><<<dim3(256, 3), 256>>>(p_mhc, p_fc2wc, fc2b, out, 2304, nullptr);
}

// round 7
// speedup vs baseline: 9.1835x; 2.4408x over previous
#include <cuda_runtime.h>
#include <cuda_fp16.h>
#include <math.h>

// ---------------- problem constants ----------------
#define LTOK 32768      // B * D*H*W
#define CDIM 192
#define NWIN 64
#define NHD  6
#define NTOK 512
#define HDD  32
#define NWH  (NWIN*NHD)   // 384

typedef unsigned int u32;
typedef __half f16;

// ---------------- device scratch (static, allocation-free) ----------------
__device__ float g_h2[LTOK * CDIM];
__device__ float g_x2[LTOK * CDIM];
__device__ float g_bias[NHD * NTOK * NTOK];
__device__ float g_pp[128 * CDIM];
__device__ float g_ca[CDIM];
// fp16 activations
__device__ f16 g_xn [LTOK * CDIM];
__device__ f16 g_ao [LTOK * CDIM];
__device__ f16 g_x2n[LTOK * CDIM];
__device__ f16 g_h1 [LTOK * 64];
__device__ f16 g_mh [(size_t)LTOK * 768];
// attention operands
__device__ f16 g_q [NWH * NTOK * HDD];   // scaled
__device__ f16 g_k [NWH * NTOK * HDD];
__device__ f16 g_vt[NWH * HDD * NTOK];   // V transposed [wh][d][tok]
// fp16 weights
__device__ f16 g_qkvw[576 * 192];
__device__ f16 g_projw[192 * 192];
__device__ f16 g_fc1w[768 * 192];
__device__ f16 g_fc2w[192 * 768];
__device__ f16 g_w1t[27 * 64 * 192];   // [kk][co][ci]
__device__ f16 g_w2t[27 * 192 * 64];

__device__ __forceinline__ float gelu_exact(float x) {
    return 0.5f * x * (1.0f + erff(x * 0.70710678118654752440f));
}
__device__ __forceinline__ u32 packh2(float a, float b) {
    __half2 t = __floats2half2_rn(a, b);
    return *(u32*)&t;
}

// ---------------- mma / ldmatrix / cp.async helpers ----------------
__device__ __forceinline__ void ldm4(u32& r0, u32& r1, u32& r2, u32& r3, const f16* p) {
    u32 addr = (u32)__cvta_generic_to_shared(p);
    asm volatile("ldmatrix.sync.aligned.m8n8.x4.shared.b16 {%0,%1,%2,%3},[%4];"
                 : "=r"(r0), "=r"(r1), "=r"(r2), "=r"(r3) : "r"(addr));
}
__device__ __forceinline__ void mma16816(float* c, const u32* a, const u32* b) {
    asm volatile(
        "mma.sync.aligned.m16n8k16.row.col.f32.f16.f16.f32 "
        "{%0,%1,%2,%3},{%4,%5,%6,%7},{%8,%9},{%0,%1,%2,%3};"
        : "+f"(c[0]), "+f"(c[1]), "+f"(c[2]), "+f"(c[3])
        : "r"(a[0]), "r"(a[1]), "r"(a[2]), "r"(a[3]), "r"(b[0]), "r"(b[1]));
}
__device__ __forceinline__ void cp16(f16* dst, const f16* src) {
    u32 d = (u32)__cvta_generic_to_shared(dst);
    asm volatile("cp.async.cg.shared.global [%0],[%1],16;" :: "r"(d), "l"(src));
}
__device__ __forceinline__ void cp16z(f16* dst, const f16* src, bool v) {
    u32 d = (u32)__cvta_generic_to_shared(dst);
    int sz = v ? 16 : 0;
    asm volatile("cp.async.cg.shared.global [%0],[%1],16,%2;" :: "r"(d), "l"(src), "r"(sz));
}
#define CP_COMMIT() asm volatile("cp.async.commit_group;")
#define CP_WAIT1()  asm volatile("cp.async.wait_group 1;")

// ---------------- LayerNorm -> fp16 ----------------
__global__ void ln_kernel(const float* __restrict__ x, const float* __restrict__ g,
                          const float* __restrict__ b, f16* __restrict__ dst) {
    int row  = blockIdx.x * blockDim.y + threadIdx.y;
    int lane = threadIdx.x;
    const float* xr = x + (size_t)row * CDIM;
    float v[6]; float s = 0.f, ss = 0.f;
#pragma unroll
    for (int i = 0; i < 6; i++) { v[i] = xr[lane + 32*i]; s += v[i]; ss += v[i]*v[i]; }
#pragma unroll
    for (int o = 16; o > 0; o >>= 1) {
        s  += __shfl_xor_sync(0xffffffffu, s, o);
        ss += __shfl_xor_sync(0xffffffffu, ss, o);
    }
    float mean = s * (1.f/192.f);
    float var  = ss * (1.f/192.f) - mean*mean;
    float rstd = rsqrtf(var + 1e-5f);
    f16* orow = dst + (size_t)row * CDIM;
#pragma unroll
    for (int i = 0; i < 6; i++) {
        int c = lane + 32*i;
        orow[c] = __float2half((v[i]-mean)*rstd*g[c] + b[c]);
    }
}

// ---------------- weight conversion kernels ----------------
__global__ void f2h_kernel(const float* __restrict__ src, f16* __restrict__ dst, int n) {
    int idx = blockIdx.x * 256 + threadIdx.x;
    if (idx < n) dst[idx] = __float2half(src[idx]);
}
__global__ void wconv1(const float* __restrict__ src) {
    int idx = blockIdx.x * 256 + threadIdx.x;
    if (idx >= 64*192*27) return;
    int co = idx / (192*27), ci = (idx / 27) % 192, kk = idx % 27;
    g_w1t[((size_t)kk*64 + co)*192 + ci] = __float2half(src[idx]);
}
__global__ void wconv2(const float* __restrict__ src) {
    int idx = blockIdx.x * 256 + threadIdx.x;
    if (idx >= 192*64*27) return;
    int co = idx / (64*27), ci = (idx / 27) % 64, kk = idx % 27;
    g_w2t[((size_t)kk*192 + co)*64 + ci] = __float2half(src[idx]);
}

// ---------------- relative-position bias gather ----------------
__global__ void bias_kernel(const int* __restrict__ rpi, const float* __restrict__ rpb) {
    int idx = blockIdx.x * 256 + threadIdx.x;
    if (idx >= NHD * NTOK * NTOK) return;
    int h  = idx / (NTOK*NTOK);
    int nm = idx % (NTOK*NTOK);
    g_bias[idx] = rpb[rpi[nm]*NHD + h];
}

// ---------------- epilogue dispatch ----------------
// EPI: 1 qkv-scatter, 2 proj+residual, 3 fc1 gelu->f16, 4 final add
template<int EPI>
__device__ __forceinline__ void epi_store(int m, int n, float v,
                                          float* __restrict__ out,
                                          const float* __restrict__ aux0) {
    if (EPI == 1) {
        int which = n / 192, c = n % 192;
        int head = c >> 5, hd = c & 31;
        int d = m >> 12, h = (m >> 6) & 63, w = m & 63;
        int wi = ((h >> 3) << 3) | (w >> 3);
        int nt = (d << 6) | ((h & 7) << 3) | (w & 7);
        int wh = wi*NHD + head;
        if (which == 0)
            g_q[((size_t)wh*NTOK + nt)*HDD + hd] = __float2half(v * 0.17677669529663687f);
        else if (which == 1)
            g_k[((size_t)wh*NTOK + nt)*HDD + hd] = __float2half(v);
        else
            g_vt[((size_t)wh*HDD + hd)*NTOK + nt] = __float2half(v);
    } else if (EPI == 2) {
        int wi = m >> 9, nt = m & 511;
        int d = nt >> 6;
        int h = ((wi >> 3) << 3) | ((nt >> 3) & 7);
        int w = ((wi & 7) << 3) | (nt & 7);
        size_t l = ((size_t)d << 12) | (h << 6) | w;
        size_t o = l*CDIM + n;
        g_x2[o] = aux0[o] + v + g_h2[o] * g_ca[n] * 0.01f;
    } else if (EPI == 3) {
        g_mh[(size_t)m * 768 + n] = __float2half(gelu_exact(v));
    } else { // EPI == 4
        out[(size_t)m*CDIM + n] = g_x2[(size_t)m*CDIM + n] + v;
    }
}

// ---------------- fp16 tensor-core GEMM, 3-stage cp.async pipeline ----------------
// out = A[M,K] @ W[N,K]^T (+bias, epilogue). K multiple of 32.
template<int EPI>
__global__ __launch_bounds__(256)
void gemm_f16(const f16* __restrict__ A, const f16* __restrict__ B,
              const float* __restrict__ bias, float* __restrict__ out,
              int Kc, const float* __restrict__ aux0) {
    __shared__ __align__(16) f16 As[3][128][40];
    __shared__ __align__(16) f16 Bs[3][64][40];
    const int m0 = blockIdx.x * 128;
    const int n0 = blockIdx.y * 64;
    const int tid = threadIdx.x;
    const int lane = tid & 31, warp = tid >> 5;
    const int warp_m = warp & 3, warp_n = warp >> 2;

    const int arow = tid >> 1, acolv = (tid & 1) * 16;
    const int brow = tid >> 2, bcolv = (tid & 3) * 8;
    const f16* aptr = A + (size_t)(m0 + arow) * Kc + acolv;
    const f16* bptr = B + (size_t)(n0 + brow) * Kc + bcolv;

    const int a_r  = warp_m*32 + (lane & 7) + ((lane >> 3) & 1) * 8;
    const int a_c8 = (lane >> 4) * 8;
    const int b_r  = warp_n*32 + (lane >> 4) * 8 + (lane & 7);
    const int b_c8 = ((lane >> 3) & 1) * 8;

    float acc[2][4][4];
#pragma unroll
    for (int i = 0; i < 2; i++)
#pragma unroll
        for (int j = 0; j < 4; j++)
#pragma unroll
            for (int t = 0; t < 4; t++) acc[i][j][t] = 0.f;

    const int nk = Kc >> 5;
    auto issue = [&](int ks) {
        if (ks < nk) {
            int s = ks % 3;
            cp16(&As[s][arow][acolv],     aptr + ks*32);
            cp16(&As[s][arow][acolv + 8], aptr + ks*32 + 8);
            cp16(&Bs[s][brow][bcolv],     bptr + ks*32);
        }
        CP_COMMIT();
    };
    issue(0); issue(1);

    for (int ks = 0; ks < nk; ks++) {
        CP_WAIT1();
        __syncthreads();
        issue(ks + 2);
        const int s = ks % 3;
#pragma unroll
        for (int half = 0; half < 2; half++) {
            u32 afr[2][4], bfr[4][2];
#pragma unroll
            for (int mt = 0; mt < 2; mt++)
                ldm4(afr[mt][0], afr[mt][1], afr[mt][2], afr[mt][3],
                     &As[s][a_r + mt*16][half*16 + a_c8]);
#pragma unroll
            for (int np = 0; np < 2; np++)
                ldm4(bfr[2*np][0], bfr[2*np][1], bfr[2*np+1][0], bfr[2*np+1][1],
                     &Bs[s][b_r + np*16][half*16 + b_c8]);
#pragma unroll
            for (int mt = 0; mt < 2; mt++)
#pragma unroll
                for (int nt = 0; nt < 4; nt++)
                    mma16816(acc[mt][nt], afr[mt], bfr[nt]);
        }
    }
#pragma unroll
    for (int mt = 0; mt < 2; mt++) {
        int mrow = m0 + warp_m*32 + mt*16 + (lane >> 2);
#pragma unroll
        for (int nt = 0; nt < 4; nt++) {
            int ncol = n0 + warp_n*32 + nt*8 + 2*(lane & 3);
            epi_store<EPI>(mrow,     ncol,     acc[mt][nt][0] + bias[ncol],   out, aux0);
            epi_store<EPI>(mrow,     ncol + 1, acc[mt][nt][1] + bias[ncol+1], out, aux0);
            epi_store<EPI>(mrow + 8, ncol,     acc[mt][nt][2] + bias[ncol],   out, aux0);
            epi_store<EPI>(mrow + 8, ncol + 1, acc[mt][nt][3] + bias[ncol+1], out, aux0);
        }
    }
}

// ---------------- fp16 tensor-core 3x3x3 conv, 3-stage cp.async ----------------
// CEPI: 0 = gelu -> g_h1 f16 (COUT=64), 1 = plain fp32 -> g_h2
template<int CEPI>
__global__ __launch_bounds__(256)
void conv_f16(const f16* __restrict__ Ain, const f16* __restrict__ Wt,
              const float* __restrict__ bias, int Kc, int COUT) {
    __shared__ __align__(16) f16 As[3][128][40];
    __shared__ __align__(16) f16 Bs[3][64][40];
    const int l0 = blockIdx.x * 128;
    const int n0 = blockIdx.y * 64;
    const int tid = threadIdx.x;
    const int lane = tid & 31, warp = tid >> 5;
    const int warp_m = warp & 3, warp_n = warp >> 2;

    const int arow = tid >> 1, acolv = (tid & 1) * 16;
    const int l = l0 + arow;
    const int d = l >> 12, hh = (l >> 6) & 63, ww = l & 63;
    const int brow = tid >> 2, bcolv = (tid & 3) * 8;

    const int a_r  = warp_m*32 + (lane & 7) + ((lane >> 3) & 1) * 8;
    const int a_c8 = (lane >> 4) * 8;
    const int b_r  = warp_n*32 + (lane >> 4) * 8 + (lane & 7);
    const int b_c8 = ((lane >> 3) & 1) * 8;

    float acc[2][4][4];
#pragma unroll
    for (int i = 0; i < 2; i++)
#pragma unroll
        for (int j = 0; j < 4; j++)
#pragma unroll
            for (int t = 0; t < 4; t++) acc[i][j][t] = 0.f;

    const int nchunk = Kc >> 5;
    const int nks = 27 * nchunk;

    auto issue = [&](int ks) {
        if (ks < nks) {
            int s = ks % 3;
            int kk = ks / nchunk, c0 = (ks % nchunk) * 32;
            int dd = kk/9 - 1, dh = (kk/3)%3 - 1, dw = kk%3 - 1;
            bool valid = ((unsigned)(d+dd) < 8u) && ((unsigned)(hh+dh) < 64u) && ((unsigned)(ww+dw) < 64u);
            const f16* p = valid ? (Ain + (size_t)(l + dd*4096 + dh*64 + dw) * Kc + c0 + acolv) : Ain;
            cp16z(&As[s][arow][acolv],     p,     valid);
            cp16z(&As[s][arow][acolv + 8], p + 8, valid);
            cp16(&Bs[s][brow][bcolv],
                 Wt + ((size_t)kk*COUT + n0 + brow) * Kc + c0 + bcolv);
        }
        CP_COMMIT();
    };
    issue(0); issue(1);

    for (int ks = 0; ks < nks; ks++) {
        CP_WAIT1();
        __syncthreads();
        issue(ks + 2);
        const int s = ks % 3;
#pragma unroll
        for (int half = 0; half < 2; half++) {
            u32 afr[2][4], bfr[4][2];
#pragma unroll
            for (int mt = 0; mt < 2; mt++)
                ldm4(afr[mt][0], afr[mt][1], afr[mt][2], afr[mt][3],
                     &As[s][a_r + mt*16][half*16 + a_c8]);
#pragma unroll
            for (int np = 0; np < 2; np++)
                ldm4(bfr[2*np][0], bfr[2*np][1], bfr[2*np+1][0], bfr[2*np+1][1],
                     &Bs[s][b_r + np*16][half*16 + b_c8]);
#pragma unroll
            for (int mt = 0; mt < 2; mt++)
#pragma unroll
                for (int nt = 0; nt < 4; nt++)
                    mma16816(acc[mt][nt], afr[mt], bfr[nt]);
        }
    }
#pragma unroll
    for (int mt = 0; mt < 2; mt++) {
        int row = warp_m*32 + mt*16 + (lane >> 2);
#pragma unroll
        for (int nt = 0; nt < 4; nt++) {
            int co = n0 + warp_n*32 + nt*8 + 2*(lane & 3);
#pragma unroll
            for (int q = 0; q < 4; q++) {
                int tok = l0 + row + (q >> 1) * 8;
                int c   = co + (q & 1);
                float v = acc[mt][nt][q] + bias[c];
                if (CEPI == 0) g_h1[(size_t)tok * 64 + c] = __float2half(gelu_exact(v));
                else           g_h2[(size_t)tok * CDIM + c] = v;
            }
        }
    }
}

// ---------------- global avg pool (stage 1) ----------------
__global__ void pool_kernel(const float* __restrict__ h2, float* __restrict__ partial) {
    int b = blockIdx.x, c = threadIdx.x;
    float s = 0.f;
    const float* base = h2 + (size_t)b * 256 * CDIM + c;
    for (int r = 0; r < 256; r++) s += base[(size_t)r * CDIM];
    partial[b*CDIM + c] = s;
}

// ---------------- channel attention (stage 2) ----------------
__global__ void ca_kernel(const float* __restrict__ partial,
                          const float* __restrict__ ca1w, const float* __restrict__ ca1b,
                          const float* __restrict__ ca2w, const float* __restrict__ ca2b) {
    __shared__ float pooled[CDIM];
    __shared__ float t6[6];
    int c = threadIdx.x;
    float s = 0.f;
    for (int b = 0; b < 128; b++) s += partial[b*CDIM + c];
    pooled[c] = s * (1.f/32768.f);
    __syncthreads();
    if (c < 6) {
        float a = ca1b[c];
        for (int i = 0; i < CDIM; i++) a += pooled[i] * ca1w[c*CDIM + i];
        t6[c] = fmaxf(a, 0.f);
    }
    __syncthreads();
    float a = ca2b[c];
#pragma unroll
    for (int j = 0; j < 6; j++) a += t6[j] * ca2w[c*6 + j];
    g_ca[c] = 1.f / (1.f + __expf(-a));
}

// ---------------- flash attention (mma.sync fp16) ----------------
// grid (4, 384): blockIdx.x = 128-query tile, blockIdx.y = wh. 256 threads.
#define QS_SZ  (128*40)
#define KS_SZ  (128*40)
#define VS_SZ  (32*136)
__global__ __launch_bounds__(256)
void fa_kernel() {
    extern __shared__ __align__(16) f16 sm[];
    f16* Qs = sm;                        // [128][40]
    f16* Ks = Qs + QS_SZ;                // [3][128][40]
    f16* Vs = Ks + 3*KS_SZ;              // [3][32][136]

    const int wh = blockIdx.y, qt = blockIdx.x;
    const int wi = wh / NHD, hh = wh % NHD;
    const int tid = threadIdx.x, lane = tid & 31, warp = tid >> 5;

    const f16* qg = g_q  + ((size_t)wh*NTOK + qt*128) * HDD;
    const f16* kg = g_k  + (size_t)wh*NTOK*HDD;
    const f16* vg = g_vt + (size_t)wh*HDD*NTOK;

    for (int c = tid; c < 512; c += 256)
        cp16(&Qs[(c>>2)*40 + (c&3)*8], qg + (c>>2)*HDD + (c&3)*8);
    auto issue_tile = [&](int j) {
        if (j < 4) {
            f16* ks = Ks + (j % 3) * KS_SZ;
            f16* vs = Vs + (j % 3) * VS_SZ;
            const f16* kt = kg + j*128*HDD;
            for (int c = tid; c < 512; c += 256) {
                cp16(&ks[(c>>2)*40 + (c&3)*8], kt + (c>>2)*HDD + (c&3)*8);
                int dv = c >> 4, ov = (c & 15) * 8;
                cp16(&vs[dv*136 + ov], vg + dv*NTOK + j*128 + ov);
            }
        }
        CP_COMMIT();
    };
    issue_tile(0);
    issue_tile(1);

    const int a_r  = warp*16 + (lane & 7) + ((lane >> 3) & 1) * 8;
    const int a_c8 = (lane >> 4) * 8;
    const int b_rr = (lane >> 4) * 8 + (lane & 7);
    const int b_c8 = ((lane >> 3) & 1) * 8;

    u32 qfr[2][4];
    float o[4][4];
#pragma unroll
    for (int i = 0; i < 4; i++)
#pragma unroll
        for (int j = 0; j < 4; j++) o[i][j] = 0.f;
    float m0 = -1e30f, m1 = -1e30f, l0 = 0.f, l1 = 0.f;

    const int nq = qt*128 + warp*16 + (lane >> 2);
    const float* bias_base = g_bias + ((size_t)hh*NTOK + nq)*NTOK + 2*(lane & 3);

    for (int j = 0; j < 4; j++) {
        CP_WAIT1();
        __syncthreads();
        if (j == 0) {
#pragma unroll
            for (int ks = 0; ks < 2; ks++)
                ldm4(qfr[ks][0], qfr[ks][1], qfr[ks][2], qfr[ks][3],
                     &Qs[a_r*40 + ks*16 + a_c8]);
        }
        issue_tile(j + 2);
        const f16* ks_s = Ks + (j % 3) * KS_SZ;
        const f16* vs_s = Vs + (j % 3) * VS_SZ;

        // ---- S = Q @ K^T ----
        float sf[16][4];
#pragma unroll
        for (int nt = 0; nt < 16; nt++)
#pragma unroll
            for (int q = 0; q < 4; q++) sf[nt][q] = 0.f;
#pragma unroll
        for (int ks = 0; ks < 2; ks++)
#pragma unroll
            for (int pr = 0; pr < 8; pr++) {
                u32 b[4];
                ldm4(b[0], b[1], b[2], b[3],
                     &ks_s[(pr*16 + b_rr)*40 + ks*16 + b_c8]);
                mma16816(sf[2*pr],     qfr[ks], b);
                mma16816(sf[2*pr + 1], qfr[ks], b + 2);
            }
        // ---- bias ----
        const float* bp = bias_base + j*128;
#pragma unroll
        for (int nt = 0; nt < 16; nt++) {
            float2 b0 = *(const float2*)(bp + nt*8);
            float2 b1 = *(const float2*)(bp + 8*NTOK + nt*8);
            sf[nt][0] += b0.x; sf[nt][1] += b0.y;
            sf[nt][2] += b1.x; sf[nt][3] += b1.y;
        }
        // ---- online softmax ----
        float mx0 = -1e30f, mx1 = -1e30f;
#pragma unroll
        for (int nt = 0; nt < 16; nt++) {
            mx0 = fmaxf(mx0, fmaxf(sf[nt][0], sf[nt][1]));
            mx1 = fmaxf(mx1, fmaxf(sf[nt][2], sf[nt][3]));
        }
        mx0 = fmaxf(mx0, __shfl_xor_sync(0xffffffffu, mx0, 1));
        mx0 = fmaxf(mx0, __shfl_xor_sync(0xffffffffu, mx0, 2));
        mx1 = fmaxf(mx1, __shfl_xor_sync(0xffffffffu, mx1, 1));
        mx1 = fmaxf(mx1, __shfl_xor_sync(0xffffffffu, mx1, 2));
        float mn0 = fmaxf(m0, mx0), mn1 = fmaxf(m1, mx1);
        float sc0 = __expf(m0 - mn0), sc1 = __expf(m1 - mn1);
        m0 = mn0; m1 = mn1;
        float rs0 = 0.f, rs1 = 0.f;
#pragma unroll
        for (int nt = 0; nt < 16; nt++) {
            sf[nt][0] = __expf(sf[nt][0] - mn0); rs0 += sf[nt][0];
            sf[nt][1] = __expf(sf[nt][1] - mn0); rs0 += sf[nt][1];
            sf[nt][2] = __expf(sf[nt][2] - mn1); rs1 += sf[nt][2];
            sf[nt][3] = __expf(sf[nt][3] - mn1); rs1 += sf[nt][3];
        }
        rs0 += __shfl_xor_sync(0xffffffffu, rs0, 1);
        rs0 += __shfl_xor_sync(0xffffffffu, rs0, 2);
        rs1 += __shfl_xor_sync(0xffffffffu, rs1, 1);
        rs1 += __shfl_xor_sync(0xffffffffu, rs1, 2);
        l0 = l0*sc0 + rs0; l1 = l1*sc1 + rs1;
#pragma unroll
        for (int dt = 0; dt < 4; dt++) {
            o[dt][0] *= sc0; o[dt][1] *= sc0;
            o[dt][2] *= sc1; o[dt][3] *= sc1;
        }
        // ---- PV ----
#pragma unroll
        for (int kt = 0; kt < 8; kt++) {
            u32 pfr[4];
            pfr[0] = packh2(sf[2*kt][0],   sf[2*kt][1]);
            pfr[1] = packh2(sf[2*kt][2],   sf[2*kt][3]);
            pfr[2] = packh2(sf[2*kt+1][0], sf[2*kt+1][1]);
            pfr[3] = packh2(sf[2*kt+1][2], sf[2*kt+1][3]);
            u32 vf[8];
            ldm4(vf[0], vf[1], vf[2], vf[3], &vs_s[b_rr*136 + kt*16 + b_c8]);
            ldm4(vf[4], vf[5], vf[6], vf[7], &vs_s[(16 + b_rr)*136 + kt*16 + b_c8]);
#pragma unroll
            for (int dt = 0; dt < 4; dt++)
                mma16816(o[dt], pfr, &vf[2*dt]);
        }
    }
    // ---- normalize + write fp16 attention output (window layout) ----
    float il0 = 1.f / l0, il1 = 1.f / l1;
    int row = wi*NTOK + qt*128 + warp*16 + (lane >> 2);
    f16* dst0 = g_ao + (size_t)row * CDIM;
    f16* dst1 = dst0 + (size_t)8 * CDIM;
#pragma unroll
    for (int dt = 0; dt < 4; dt++) {
        int c = hh*HDD + dt*8 + 2*(lane & 3);
        dst0[c]     = __float2half(o[dt][0]*il0);
        dst0[c + 1] = __float2half(o[dt][1]*il0);
        dst1[c]     = __float2half(o[dt][2]*il1);
        dst1[c + 1] = __float2half(o[dt][3]*il1);
    }
}

// ---------------- launch ----------------
extern "C" void kernel_launch(void* const* d_in, const int* in_sizes, int n_in,
                              void* d_out, int out_size) {
    const float* x     = (const float*)d_in[0];
    const float* n1g   = (const float*)d_in[1];
    const float* n1b   = (const float*)d_in[2];
    const float* qkvw  = (const float*)d_in[3];
    const float* qkvb  = (const float*)d_in[4];
    const float* rpb   = (const float*)d_in[5];
    const float* projw = (const float*)d_in[6];
    const float* projb = (const float*)d_in[7];
    const float* c1w   = (const float*)d_in[8];
    const float* c1b   = (const float*)d_in[9];
    const float* c2w   = (const float*)d_in[10];
    const float* c2b   = (const float*)d_in[11];
    const float* ca1w  = (const float*)d_in[12];
    const float* ca1b  = (const float*)d_in[13];
    const float* ca2w  = (const float*)d_in[14];
    const float* ca2b  = (const float*)d_in[15];
    const float* n2g   = (const float*)d_in[16];
    const float* n2b   = (const float*)d_in[17];
    const float* fc1w  = (const float*)d_in[18];
    const float* fc1b  = (const float*)d_in[19];
    const float* fc2w  = (const float*)d_in[20];
    const float* fc2b  = (const float*)d_in[21];
    const int*   rpi   = (const int*)d_in[22];
    float* out = (float*)d_out;

    f16 *p_xn, *p_ao, *p_x2n, *p_h1, *p_mh;
    f16 *p_qkvw, *p_projw, *p_fc1w, *p_fc2w, *p_w1t, *p_w2t;
    float *p_h2, *p_x2, *p_pp;
    cudaGetSymbolAddress((void**)&p_xn,    g_xn);
    cudaGetSymbolAddress((void**)&p_ao,    g_ao);
    cudaGetSymbolAddress((void**)&p_x2n,   g_x2n);
    cudaGetSymbolAddress((void**)&p_h1,    g_h1);
    cudaGetSymbolAddress((void**)&p_mh,    g_mh);
    cudaGetSymbolAddress((void**)&p_qkvw,  g_qkvw);
    cudaGetSymbolAddress((void**)&p_projw, g_projw);
    cudaGetSymbolAddress((void**)&p_fc1w,  g_fc1w);
    cudaGetSymbolAddress((void**)&p_fc2w,  g_fc2w);
    cudaGetSymbolAddress((void**)&p_w1t,   g_w1t);
    cudaGetSymbolAddress((void**)&p_w2t,   g_w2t);
    cudaGetSymbolAddress((void**)&p_h2,    g_h2);
    cudaGetSymbolAddress((void**)&p_x2,    g_x2);
    cudaGetSymbolAddress((void**)&p_pp,    g_pp);

    const int fa_smem = (QS_SZ + 3*KS_SZ + 3*VS_SZ) * (int)sizeof(f16);
    cudaFuncSetAttribute(fa_kernel, cudaFuncAttributeMaxDynamicSharedMemorySize, fa_smem);

    // 1) weight conversions + bias gather (small)
    f2h_kernel<<<(576*192 + 255)/256, 256>>>(qkvw, p_qkvw, 576*192);
    f2h_kernel<<<(192*192 + 255)/256, 256>>>(projw, p_projw, 192*192);
    f2h_kernel<<<(768*192 + 255)/256, 256>>>(fc1w, p_fc1w, 768*192);
    f2h_kernel<<<(192*768 + 255)/256, 256>>>(fc2w, p_fc2w, 192*768);
    wconv1<<<(64*192*27 + 255)/256, 256>>>(c1w);
    wconv2<<<(192*64*27 + 255)/256, 256>>>(c2w);
    bias_kernel<<<(NHD*NTOK*NTOK + 255)/256, 256>>>(rpi, rpb);
    // 2) LN1 -> fp16
    ln_kernel<<<4096, dim3(32, 8)>>>(x, n1g, n1b, p_xn);
    // 3) QKV projection -> attention operands
    gemm_f16<1><<<dim3(256, 9), 256>>>(p_xn, p_qkvw, qkvb, nullptr, 192, nullptr);
    // 4) conv branch
    conv_f16<0><<<dim3(256, 1), 256>>>(p_xn, p_w1t, c1b, 192, 64);
    conv_f16<1><<<dim3(256, 3), 256>>>(p_h1, p_w2t, c2b, 64, 192);
    pool_kernel<<<128, CDIM>>>(p_h2, p_pp);
    ca_kernel<<<1, CDIM>>>(p_pp, ca1w, ca1b, ca2w, ca2b);
    // 5) flash attention
    fa_kernel<<<dim3(4, NWH), 256, fa_smem>>>();
    // 6) proj + window reverse + residual + conv*0.01 -> g_x2
    gemm_f16<2><<<dim3(256, 3), 256>>>(p_ao, p_projw, projb, nullptr, 192, x);
    // 7) LN2 + MLP
    ln_kernel<<<4096, dim3(32, 8)>>>(p_x2, n2g, n2b, p_x2n);
    gemm_f16<3><<<dim3(256, 12), 256>>>(p_x2n, p_fc1w, fc1b, nullptr, 192, nullptr);
    gemm_f16<4><<<dim3(256, 3), 256>>>(p_mh, p_fc2w, fc2b, out, 768, nullptr);
}